// round 1
// baseline (speedup 1.0000x reference)
#include <cuda_runtime.h>
#include <math.h>

#define B 4
#define T 4096
#define CDIM 2048
#define H 128
#define NROWS (B*T)

// Scratch for Q/K/V projections (8 MB each) — __device__ globals per harness rules.
__device__ float g_Q[NROWS*H];
__device__ float g_K[NROWS*H];
__device__ float g_V[NROWS*H];

// ============================================================
// Kernel 1: fused QKV projection  out[n][h] = sum_c x[n][c]*W[c][h]
// 64x64x16 tiles, 256 threads, 4x4 micro-tile, float4 everywhere.
// ============================================================
#define PBM 64
#define PBN 64
#define PBK 16
#define PSTR 68   // padded stride (floats); 68*4 bytes is 16B-multiple -> float4-aligned rows

__global__ __launch_bounds__(256)
void proj_kernel(const float* __restrict__ x,
                 const float* __restrict__ Wq,
                 const float* __restrict__ Wk,
                 const float* __restrict__ Wv)
{
    __shared__ float Xs[PBK*PSTR];   // [k][m]
    __shared__ float Ws[PBK*PSTR];   // [k][n]

    int tid = threadIdx.x;
    int ty = tid >> 4, tx = tid & 15;
    int rowBase = blockIdx.x * PBM;
    int wsel    = blockIdx.y >> 1;   // 0=Q,1=K,2=V
    int colTile = blockIdx.y & 1;    // H=128 -> two 64-wide col tiles
    const float* W = (wsel == 0) ? Wq : (wsel == 1) ? Wk : Wv;
    float* outp    = (wsel == 0) ? g_Q : (wsel == 1) ? g_K : g_V;

    int xm = tid >> 2;              // 0..63   (row within tile)
    int xk = (tid & 3) * 4;         // 0,4,8,12
    int wk = tid >> 4;              // 0..15
    int wn = (tid & 15) * 4;        // 0..60

    float acc[4][4];
    #pragma unroll
    for (int i = 0; i < 4; i++)
        #pragma unroll
        for (int j = 0; j < 4; j++) acc[i][j] = 0.f;

    for (int kb = 0; kb < CDIM; kb += PBK) {
        float4 xv = *(const float4*)&x[(size_t)(rowBase + xm) * CDIM + kb + xk];
        float4 wv = *(const float4*)&W[(size_t)(kb + wk) * H + colTile * 64 + wn];
        Xs[(xk+0)*PSTR + xm] = xv.x;
        Xs[(xk+1)*PSTR + xm] = xv.y;
        Xs[(xk+2)*PSTR + xm] = xv.z;
        Xs[(xk+3)*PSTR + xm] = xv.w;
        *(float4*)&Ws[wk*PSTR + wn] = wv;
        __syncthreads();

        #pragma unroll
        for (int k = 0; k < PBK; k++) {
            float4 a  = *(float4*)&Xs[k*PSTR + ty*4];
            float4 bb = *(float4*)&Ws[k*PSTR + tx*4];
            float am[4] = {a.x, a.y, a.z, a.w};
            float bn[4] = {bb.x, bb.y, bb.z, bb.w};
            #pragma unroll
            for (int i = 0; i < 4; i++)
                #pragma unroll
                for (int j = 0; j < 4; j++)
                    acc[i][j] += am[i] * bn[j];
        }
        __syncthreads();
    }

    #pragma unroll
    for (int i = 0; i < 4; i++) {
        float4 v = make_float4(acc[i][0], acc[i][1], acc[i][2], acc[i][3]);
        *(float4*)&outp[(size_t)(rowBase + ty*4 + i) * H + colTile * 64 + tx*4] = v;
    }
}

// ============================================================
// Kernel 2: causal flash attention, fp32
// Block = (batch b, 64-query tile). BKV = 64. 256 threads.
// Q,K stored transposed [d][q] in smem -> conflict-free float4 operand reads.
// ============================================================
#define AQ  64
#define AKV 64
#define ASTR 68

// smem carve (floats)
#define SM_QS 0
#define SM_KS (SM_QS + H*ASTR)          // 8704
#define SM_VS (SM_KS + H*ASTR)          // 8704
#define SM_PS (SM_VS + AKV*H)           // 8192
#define SM_M  (SM_PS + AKV*ASTR)        // 4352
#define SM_L  (SM_M + 64)
#define SM_SC (SM_L + 64)
#define SM_TOT (SM_SC + 64)             // 30144 floats = 120576 bytes

__global__ __launch_bounds__(256)
void attn_kernel(float* __restrict__ out)
{
    extern __shared__ float sm[];
    float* Qs    = sm + SM_QS;   // [d][q]
    float* Ks    = sm + SM_KS;   // [d][kv]
    float* Vs    = sm + SM_VS;   // [kv][d]
    float* Ps    = sm + SM_PS;   // [kv][q]
    float* rowM  = sm + SM_M;
    float* rowL  = sm + SM_L;
    float* rowSc = sm + SM_SC;

    int tid = threadIdx.x;
    int ty = tid >> 4, tx = tid & 15;
    int b = blockIdx.y;
    int qBase = blockIdx.x * AQ;
    const float scaleAttn = powf((float)CDIM, -0.05f);   // NOTE: exponent is -0.05 per reference

    // Load Q tile transposed (scale folded into Q)
    #pragma unroll
    for (int i = 0; i < 8; i++) {
        int l  = tid + i * 256;        // float4 index, 0..2047
        int q  = l >> 5;               // 32 float4 per row
        int d0 = (l & 31) << 2;
        float4 v = *(const float4*)&g_Q[(size_t)(b*T + qBase + q) * H + d0];
        Qs[(d0+0)*ASTR + q] = v.x * scaleAttn;
        Qs[(d0+1)*ASTR + q] = v.y * scaleAttn;
        Qs[(d0+2)*ASTR + q] = v.z * scaleAttn;
        Qs[(d0+3)*ASTR + q] = v.w * scaleAttn;
    }
    if (tid < 64) { rowM[tid] = -1e30f; rowL[tid] = 0.f; }

    float acc[4][8];
    #pragma unroll
    for (int i = 0; i < 4; i++)
        #pragma unroll
        for (int j = 0; j < 8; j++) acc[i][j] = 0.f;

    for (int kvBase = 0; kvBase <= qBase; kvBase += AKV) {
        // Load K transposed
        #pragma unroll
        for (int i = 0; i < 8; i++) {
            int l  = tid + i * 256;
            int kv = l >> 5;
            int d0 = (l & 31) << 2;
            float4 v = *(const float4*)&g_K[(size_t)(b*T + kvBase + kv) * H + d0];
            Ks[(d0+0)*ASTR + kv] = v.x;
            Ks[(d0+1)*ASTR + kv] = v.y;
            Ks[(d0+2)*ASTR + kv] = v.z;
            Ks[(d0+3)*ASTR + kv] = v.w;
        }
        // Load V straight
        #pragma unroll
        for (int i = 0; i < 8; i++) {
            int l  = tid + i * 256;
            int kv = l >> 5;
            int d0 = (l & 31) << 2;
            *(float4*)&Vs[kv*H + d0] =
                *(const float4*)&g_V[(size_t)(b*T + kvBase + kv) * H + d0];
        }
        __syncthreads();

        // S = Q'·K^T  (4x4 per thread)
        float s[4][4];
        #pragma unroll
        for (int i = 0; i < 4; i++)
            #pragma unroll
            for (int j = 0; j < 4; j++) s[i][j] = 0.f;

        #pragma unroll 4
        for (int d = 0; d < H; d++) {
            float4 a  = *(float4*)&Qs[d*ASTR + ty*4];
            float4 bb = *(float4*)&Ks[d*ASTR + tx*4];
            float am[4] = {a.x, a.y, a.z, a.w};
            float bn[4] = {bb.x, bb.y, bb.z, bb.w};
            #pragma unroll
            for (int i = 0; i < 4; i++)
                #pragma unroll
                for (int j = 0; j < 4; j++)
                    s[i][j] += am[i] * bn[j];
        }

        // Causal mask: only the diagonal tile is partial
        if (kvBase == qBase) {
            #pragma unroll
            for (int i = 0; i < 4; i++)
                #pragma unroll
                for (int j = 0; j < 4; j++)
                    if (tx*4 + j > ty*4 + i) s[i][j] = -1e30f;
        }

        // Online softmax (row = ty*4+i, reduce across the 16 tx lanes)
        float p[4][4], myScale[4], myNewM[4], mySum[4];
        #pragma unroll
        for (int i = 0; i < 4; i++) {
            float mx = fmaxf(fmaxf(s[i][0], s[i][1]), fmaxf(s[i][2], s[i][3]));
            #pragma unroll
            for (int off = 8; off >= 1; off >>= 1)
                mx = fmaxf(mx, __shfl_xor_sync(0xffffffffu, mx, off, 16));
            int q = ty*4 + i;
            float mPrev = rowM[q];
            float mNew  = fmaxf(mPrev, mx);
            float sum = 0.f;
            #pragma unroll
            for (int j = 0; j < 4; j++) { p[i][j] = __expf(s[i][j] - mNew); sum += p[i][j]; }
            #pragma unroll
            for (int off = 8; off >= 1; off >>= 1)
                sum += __shfl_xor_sync(0xffffffffu, sum, off, 16);
            myScale[i] = __expf(mPrev - mNew);
            myNewM[i]  = mNew;
            mySum[i]   = sum;
        }
        // One lane per row publishes stats (reads above completed: shuffles synced)
        if (tx == 0) {
            #pragma unroll
            for (int i = 0; i < 4; i++) {
                int q = ty*4 + i;
                rowM[q]  = myNewM[i];
                rowSc[q] = myScale[i];
                rowL[q]  = rowL[q] * myScale[i] + mySum[i];
            }
        }
        // Stage P transposed [kv][q] for the PV GEMM
        #pragma unroll
        for (int i = 0; i < 4; i++)
            #pragma unroll
            for (int j = 0; j < 4; j++)
                Ps[(tx*4 + j)*ASTR + ty*4 + i] = p[i][j];
        __syncthreads();

        // Rescale accumulator, then O += P·V  (4x8 per thread)
        #pragma unroll
        for (int i = 0; i < 4; i++) {
            float sc = rowSc[ty*4 + i];
            #pragma unroll
            for (int j = 0; j < 8; j++) acc[i][j] *= sc;
        }
        #pragma unroll 2
        for (int kv = 0; kv < AKV; kv++) {
            float4 pv = *(float4*)&Ps[kv*ASTR + ty*4];
            float pm[4] = {pv.x, pv.y, pv.z, pv.w};
            float4 v0 = *(float4*)&Vs[kv*H + tx*8];
            float4 v1 = *(float4*)&Vs[kv*H + tx*8 + 4];
            float vn[8] = {v0.x, v0.y, v0.z, v0.w, v1.x, v1.y, v1.z, v1.w};
            #pragma unroll
            for (int i = 0; i < 4; i++)
                #pragma unroll
                for (int j = 0; j < 8; j++)
                    acc[i][j] += pm[i] * vn[j];
        }
        __syncthreads();   // protect Ks/Vs/Ps/rowSc before next tile
    }

    // Epilogue: divide by l, store
    #pragma unroll
    for (int i = 0; i < 4; i++) {
        int q = ty*4 + i;
        float inv = 1.0f / rowL[q];
        float4 o0 = make_float4(acc[i][0]*inv, acc[i][1]*inv, acc[i][2]*inv, acc[i][3]*inv);
        float4 o1 = make_float4(acc[i][4]*inv, acc[i][5]*inv, acc[i][6]*inv, acc[i][7]*inv);
        size_t base = (size_t)(b*T + qBase + q) * H + tx*8;
        *(float4*)&out[base]     = o0;
        *(float4*)&out[base + 4] = o1;
    }
}

extern "C" void kernel_launch(void* const* d_in, const int* in_sizes, int n_in,
                              void* d_out, int out_size)
{
    const float* x  = (const float*)d_in[0];
    const float* Wq = (const float*)d_in[1];
    const float* Wk = (const float*)d_in[2];
    const float* Wv = (const float*)d_in[3];
    float* out = (float*)d_out;

    // Opt-in to >48KB dynamic smem. Called every launch (idempotent); on the
    // first (correctness) call it takes effect, so the capture-time launch is safe.
    cudaFuncSetAttribute(attn_kernel, cudaFuncAttributeMaxDynamicSharedMemorySize,
                         SM_TOT * (int)sizeof(float));

    proj_kernel<<<dim3(NROWS / PBM, 6), 256>>>(x, Wq, Wk, Wv);
    attn_kernel<<<dim3(T / AQ, B), 256, SM_TOT * sizeof(float)>>>(out);
}

// round 7
// speedup vs baseline: 1.3278x; 1.3278x over previous
#include <cuda_runtime.h>
#include <cuda_bf16.h>
#include <cstdint>
#include <math.h>

#define B 4
#define T 4096
#define CDIM 2048
#define H 128
#define NROWS (B*T)

// Scratch (device globals per harness rules)
__device__ float g_Q[NROWS*H];
__device__ float g_K[NROWS*H];
__device__ float g_V[NROWS*H];
__device__ __nv_bfloat16 g_xh[NROWS*CDIM];     // x hi split
__device__ __nv_bfloat16 g_xl[NROWS*CDIM];     // x lo split
__device__ __nv_bfloat16 g_Wh[3*H*CDIM];       // W packed [w][n][k] hi
__device__ __nv_bfloat16 g_Wl[3*H*CDIM];       // W packed [w][n][k] lo

__device__ __forceinline__ uint32_t smem_u32(const void* p) {
    uint32_t a;
    asm("{ .reg .u64 t; cvta.to.shared.u64 t, %1; cvt.u32.u64 %0, t; }" : "=r"(a) : "l"(p));
    return a;
}

__device__ __forceinline__ void cp_async16(uint32_t dst, const void* src) {
    asm volatile("cp.async.cg.shared.global [%0], [%1], 16;" :: "r"(dst), "l"(src) : "memory");
}
#define CP_COMMIT() asm volatile("cp.async.commit_group;" ::: "memory")
#define CP_WAIT1()  asm volatile("cp.async.wait_group 1;" ::: "memory")

__device__ __forceinline__ void ldsm4(uint32_t addr, uint32_t* r) {
    asm volatile("ldmatrix.sync.aligned.m8n8.x4.shared.b16 {%0,%1,%2,%3}, [%4];"
        : "=r"(r[0]), "=r"(r[1]), "=r"(r[2]), "=r"(r[3]) : "r"(addr));
}

__device__ __forceinline__ void mma16816(float* c, const uint32_t* a, uint32_t b0, uint32_t b1) {
    asm volatile("mma.sync.aligned.m16n8k16.row.col.f32.bf16.bf16.f32 "
        "{%0,%1,%2,%3}, {%4,%5,%6,%7}, {%8,%9}, {%0,%1,%2,%3};"
        : "+f"(c[0]), "+f"(c[1]), "+f"(c[2]), "+f"(c[3])
        : "r"(a[0]), "r"(a[1]), "r"(a[2]), "r"(a[3]), "r"(b0), "r"(b1));
}

// ============================================================
// Split kernels: fp32 -> bf16 hi + lo
// ============================================================
__global__ __launch_bounds__(256) void split_x_kernel(const float* __restrict__ x)
{
    int i = blockIdx.x * 256 + threadIdx.x;   // float4 index
    float4 v = ((const float4*)x)[i];
    __nv_bfloat16 h0 = __float2bfloat16_rn(v.x);
    __nv_bfloat16 h1 = __float2bfloat16_rn(v.y);
    __nv_bfloat16 h2 = __float2bfloat16_rn(v.z);
    __nv_bfloat16 h3 = __float2bfloat16_rn(v.w);
    __nv_bfloat16 l0 = __float2bfloat16_rn(v.x - __bfloat162float(h0));
    __nv_bfloat16 l1 = __float2bfloat16_rn(v.y - __bfloat162float(h1));
    __nv_bfloat16 l2 = __float2bfloat16_rn(v.z - __bfloat162float(h2));
    __nv_bfloat16 l3 = __float2bfloat16_rn(v.w - __bfloat162float(h3));
    __nv_bfloat162* ph = (__nv_bfloat162*)g_xh;
    __nv_bfloat162* pl = (__nv_bfloat162*)g_xl;
    ph[2*i]   = __halves2bfloat162(h0, h1);
    ph[2*i+1] = __halves2bfloat162(h2, h3);
    pl[2*i]   = __halves2bfloat162(l0, l1);
    pl[2*i+1] = __halves2bfloat162(l2, l3);
}

// Pack W[c][h] -> g_W*[w][n][k] (transpose) with hi/lo split
__global__ __launch_bounds__(256) void split_w_kernel(const float* __restrict__ Wq,
                                                      const float* __restrict__ Wk,
                                                      const float* __restrict__ Wv)
{
    int w = blockIdx.y;
    const float* W = (w == 0) ? Wq : (w == 1) ? Wk : Wv;
    int idx = blockIdx.x * 256 + threadIdx.x;   // n*2048 + k
    int n = idx >> 11;
    int k = idx & 2047;
    float v = W[(size_t)k * H + n];
    __nv_bfloat16 h = __float2bfloat16_rn(v);
    __nv_bfloat16 l = __float2bfloat16_rn(v - __bfloat162float(h));
    g_Wh[(size_t)w * H * CDIM + idx] = h;
    g_Wl[(size_t)w * H * CDIM + idx] = l;
}

// ============================================================
// HMMA projection GEMM: out[128m x 128n] = x @ W  (hi/lo split: hh + hl + lh)
// CTA 128x128, 8 warps (4m x 2n), warp tile 32x64, K-chunk 32, 3-stage cp.async.
// smem rows padded to 80B (stride 5*16B, gcd(5,8)=1 -> ldmatrix conflict-free).
// ============================================================
#define KC 32
#define NITER (CDIM / KC)          // 64
#define RSB 80                     // row stride bytes (32 bf16 data + 8 pad)
#define MAT_B (128 * RSB)          // 10240
#define STAGE_B (4 * MAT_B)        // 40960: Ah, Al, Bh, Bl
#define NSTAGE 3
#define MM_SMEM (NSTAGE * STAGE_B) // 122880

__global__ __launch_bounds__(256, 1)
void mm_kernel()
{
    extern __shared__ char dsm[];
    uint32_t sb = smem_u32(dsm);
    int tid = threadIdx.x;
    int lid = tid & 31, wid = tid >> 5;
    int wm = wid & 3, wn = wid >> 2;
    int mBase = blockIdx.x * 128;
    int wsel  = blockIdx.y;
    int nBase = wsel * 128;

    // per-thread load coords: 8 cp.async per stage (2 chunks x 4 matrices)
    int r0 = tid >> 2, c0 = (tid & 3);            // chunk 0: rows 0..63
    int r1 = (tid + 256) >> 2, c1 = (tid & 3);    // chunk 1: rows 64..127

    float acc[2][8][4];
    #pragma unroll
    for (int mt = 0; mt < 2; mt++)
        #pragma unroll
        for (int nt = 0; nt < 8; nt++)
            #pragma unroll
            for (int e = 0; e < 4; e++) acc[mt][nt][e] = 0.f;

    auto load_stage = [&](int stage, int k0) {
        uint32_t s = sb + stage * STAGE_B;
        const __nv_bfloat16* xh = g_xh + (size_t)(mBase + r0) * CDIM + k0 + c0 * 8;
        const __nv_bfloat16* xl = g_xl + (size_t)(mBase + r0) * CDIM + k0 + c0 * 8;
        const __nv_bfloat16* wh = g_Wh + (size_t)(nBase + r0) * CDIM + k0 + c0 * 8;
        const __nv_bfloat16* wl = g_Wl + (size_t)(nBase + r0) * CDIM + k0 + c0 * 8;
        uint32_t d = s + r0 * RSB + c0 * 16;
        cp_async16(d + 0*MAT_B, xh);
        cp_async16(d + 1*MAT_B, xl);
        cp_async16(d + 2*MAT_B, wh);
        cp_async16(d + 3*MAT_B, wl);
        xh = g_xh + (size_t)(mBase + r1) * CDIM + k0 + c1 * 8;
        xl = g_xl + (size_t)(mBase + r1) * CDIM + k0 + c1 * 8;
        wh = g_Wh + (size_t)(nBase + r1) * CDIM + k0 + c1 * 8;
        wl = g_Wl + (size_t)(nBase + r1) * CDIM + k0 + c1 * 8;
        d = s + r1 * RSB + c1 * 16;
        cp_async16(d + 0*MAT_B, xh);
        cp_async16(d + 1*MAT_B, xl);
        cp_async16(d + 2*MAT_B, wh);
        cp_async16(d + 3*MAT_B, wl);
    };

    load_stage(0, 0);  CP_COMMIT();
    load_stage(1, KC); CP_COMMIT();

    int lrow = lid & 15, lkh = lid >> 4;   // ldmatrix lane -> row-in-16 / k-half

    for (int it = 0; it < NITER; it++) {
        CP_WAIT1();
        __syncthreads();
        if (it + 2 < NITER) load_stage((it + 2) % NSTAGE, (it + 2) * KC);
        CP_COMMIT();

        uint32_t s = sb + (it % NSTAGE) * STAGE_B;
        #pragma unroll
        for (int ks = 0; ks < 2; ks++) {
            uint32_t kOff = ks * 32 + lkh * 16;
            uint32_t a_hi[2][4], a_lo[2][4];
            #pragma unroll
            for (int mt = 0; mt < 2; mt++) {
                uint32_t ra = (wm * 32 + mt * 16 + lrow) * RSB + kOff;
                ldsm4(s + 0*MAT_B + ra, a_hi[mt]);
                ldsm4(s + 1*MAT_B + ra, a_lo[mt]);
            }
            uint32_t b_hi[4][4], b_lo[4][4];
            #pragma unroll
            for (int j = 0; j < 4; j++) {
                uint32_t rb = (wn * 64 + j * 16 + lrow) * RSB + kOff;
                ldsm4(s + 2*MAT_B + rb, b_hi[j]);
                ldsm4(s + 3*MAT_B + rb, b_lo[j]);
            }
            #pragma unroll
            for (int mt = 0; mt < 2; mt++)
                #pragma unroll
                for (int nt = 0; nt < 8; nt++) {
                    int j = nt >> 1, sel = nt & 1;
                    uint32_t bh0 = b_hi[j][sel], bh1 = b_hi[j][sel + 2];
                    uint32_t bl0 = b_lo[j][sel], bl1 = b_lo[j][sel + 2];
                    mma16816(acc[mt][nt], a_hi[mt], bh0, bh1);
                    mma16816(acc[mt][nt], a_hi[mt], bl0, bl1);
                    mma16816(acc[mt][nt], a_lo[mt], bh0, bh1);
                }
        }
        __syncthreads();
    }

    float* outp = (wsel == 0) ? g_Q : (wsel == 1) ? g_K : g_V;
    #pragma unroll
    for (int mt = 0; mt < 2; mt++)
        #pragma unroll
        for (int nt = 0; nt < 8; nt++) {
            int row = mBase + wm * 32 + mt * 16 + (lid >> 2);
            int col = wn * 64 + nt * 8 + 2 * (lid & 3);
            *(float2*)&outp[(size_t)row * H + col] = make_float2(acc[mt][nt][0], acc[mt][nt][1]);
            *(float2*)&outp[(size_t)(row + 8) * H + col] = make_float2(acc[mt][nt][2], acc[mt][nt][3]);
        }
}

// ============================================================
// Kernel 2: causal flash attention, fp32 (R1-verified, big-tiles-first remap)
// ============================================================
#define AQ  64
#define AKV 64
#define ASTR 68

#define SM_QS 0
#define SM_KS (SM_QS + H*ASTR)
#define SM_VS (SM_KS + H*ASTR)
#define SM_PS (SM_VS + AKV*H)
#define SM_M  (SM_PS + AKV*ASTR)
#define SM_L  (SM_M + 64)
#define SM_SC (SM_L + 64)
#define SM_TOT (SM_SC + 64)

__global__ __launch_bounds__(256)
void attn_kernel(float* __restrict__ out)
{
    extern __shared__ float sm[];
    float* Qs    = sm + SM_QS;
    float* Ks    = sm + SM_KS;
    float* Vs    = sm + SM_VS;
    float* Ps    = sm + SM_PS;
    float* rowM  = sm + SM_M;
    float* rowL  = sm + SM_L;
    float* rowSc = sm + SM_SC;

    int tid = threadIdx.x;
    int ty = tid >> 4, tx = tid & 15;
    int b = blockIdx.y;
    int qTile = (int)gridDim.x - 1 - (int)blockIdx.x;   // biggest causal tiles first
    int qBase = qTile * AQ;
    const float scaleAttn = powf((float)CDIM, -0.05f);

    #pragma unroll
    for (int i = 0; i < 8; i++) {
        int l  = tid + i * 256;
        int q  = l >> 5;
        int d0 = (l & 31) << 2;
        float4 v = *(const float4*)&g_Q[(size_t)(b*T + qBase + q) * H + d0];
        Qs[(d0+0)*ASTR + q] = v.x * scaleAttn;
        Qs[(d0+1)*ASTR + q] = v.y * scaleAttn;
        Qs[(d0+2)*ASTR + q] = v.z * scaleAttn;
        Qs[(d0+3)*ASTR + q] = v.w * scaleAttn;
    }
    if (tid < 64) { rowM[tid] = -1e30f; rowL[tid] = 0.f; }

    float acc[4][8];
    #pragma unroll
    for (int i = 0; i < 4; i++)
        #pragma unroll
        for (int j = 0; j < 8; j++) acc[i][j] = 0.f;

    for (int kvBase = 0; kvBase <= qBase; kvBase += AKV) {
        #pragma unroll
        for (int i = 0; i < 8; i++) {
            int l  = tid + i * 256;
            int kv = l >> 5;
            int d0 = (l & 31) << 2;
            float4 v = *(const float4*)&g_K[(size_t)(b*T + kvBase + kv) * H + d0];
            Ks[(d0+0)*ASTR + kv] = v.x;
            Ks[(d0+1)*ASTR + kv] = v.y;
            Ks[(d0+2)*ASTR + kv] = v.z;
            Ks[(d0+3)*ASTR + kv] = v.w;
        }
        #pragma unroll
        for (int i = 0; i < 8; i++) {
            int l  = tid + i * 256;
            int kv = l >> 5;
            int d0 = (l & 31) << 2;
            *(float4*)&Vs[kv*H + d0] =
                *(const float4*)&g_V[(size_t)(b*T + kvBase + kv) * H + d0];
        }
        __syncthreads();

        float s[4][4];
        #pragma unroll
        for (int i = 0; i < 4; i++)
            #pragma unroll
            for (int j = 0; j < 4; j++) s[i][j] = 0.f;

        #pragma unroll 4
        for (int d = 0; d < H; d++) {
            float4 a  = *(float4*)&Qs[d*ASTR + ty*4];
            float4 bb = *(float4*)&Ks[d*ASTR + tx*4];
            float am[4] = {a.x, a.y, a.z, a.w};
            float bn[4] = {bb.x, bb.y, bb.z, bb.w};
            #pragma unroll
            for (int i = 0; i < 4; i++)
                #pragma unroll
                for (int j = 0; j < 4; j++)
                    s[i][j] += am[i] * bn[j];
        }

        if (kvBase == qBase) {
            #pragma unroll
            for (int i = 0; i < 4; i++)
                #pragma unroll
                for (int j = 0; j < 4; j++)
                    if (tx*4 + j > ty*4 + i) s[i][j] = -1e30f;
        }

        float p[4][4], myScale[4], myNewM[4], mySum[4];
        #pragma unroll
        for (int i = 0; i < 4; i++) {
            float mx = fmaxf(fmaxf(s[i][0], s[i][1]), fmaxf(s[i][2], s[i][3]));
            #pragma unroll
            for (int off = 8; off >= 1; off >>= 1)
                mx = fmaxf(mx, __shfl_xor_sync(0xffffffffu, mx, off, 16));
            int q = ty*4 + i;
            float mPrev = rowM[q];
            float mNew  = fmaxf(mPrev, mx);
            float sum = 0.f;
            #pragma unroll
            for (int j = 0; j < 4; j++) { p[i][j] = __expf(s[i][j] - mNew); sum += p[i][j]; }
            #pragma unroll
            for (int off = 8; off >= 1; off >>= 1)
                sum += __shfl_xor_sync(0xffffffffu, sum, off, 16);
            myScale[i] = __expf(mPrev - mNew);
            myNewM[i]  = mNew;
            mySum[i]   = sum;
        }
        if (tx == 0) {
            #pragma unroll
            for (int i = 0; i < 4; i++) {
                int q = ty*4 + i;
                rowM[q]  = myNewM[i];
                rowSc[q] = myScale[i];
                rowL[q]  = rowL[q] * myScale[i] + mySum[i];
            }
        }
        #pragma unroll
        for (int i = 0; i < 4; i++)
            #pragma unroll
            for (int j = 0; j < 4; j++)
                Ps[(tx*4 + j)*ASTR + ty*4 + i] = p[i][j];
        __syncthreads();

        #pragma unroll
        for (int i = 0; i < 4; i++) {
            float sc = rowSc[ty*4 + i];
            #pragma unroll
            for (int j = 0; j < 8; j++) acc[i][j] *= sc;
        }
        #pragma unroll 2
        for (int kv = 0; kv < AKV; kv++) {
            float4 pv = *(float4*)&Ps[kv*ASTR + ty*4];
            float pm[4] = {pv.x, pv.y, pv.z, pv.w};
            float4 v0 = *(float4*)&Vs[kv*H + tx*8];
            float4 v1 = *(float4*)&Vs[kv*H + tx*8 + 4];
            float vn[8] = {v0.x, v0.y, v0.z, v0.w, v1.x, v1.y, v1.z, v1.w};
            #pragma unroll
            for (int i = 0; i < 4; i++)
                #pragma unroll
                for (int j = 0; j < 8; j++)
                    acc[i][j] += pm[i] * vn[j];
        }
        __syncthreads();
    }

    #pragma unroll
    for (int i = 0; i < 4; i++) {
        int q = ty*4 + i;
        float inv = 1.0f / rowL[q];
        float4 o0 = make_float4(acc[i][0]*inv, acc[i][1]*inv, acc[i][2]*inv, acc[i][3]*inv);
        float4 o1 = make_float4(acc[i][4]*inv, acc[i][5]*inv, acc[i][6]*inv, acc[i][7]*inv);
        size_t base = (size_t)(b*T + qBase + q) * H + tx*8;
        *(float4*)&out[base]     = o0;
        *(float4*)&out[base + 4] = o1;
    }
}

extern "C" void kernel_launch(void* const* d_in, const int* in_sizes, int n_in,
                              void* d_out, int out_size)
{
    const float* x  = (const float*)d_in[0];
    const float* Wq = (const float*)d_in[1];
    const float* Wk = (const float*)d_in[2];
    const float* Wv = (const float*)d_in[3];
    float* out = (float*)d_out;

    cudaFuncSetAttribute(mm_kernel, cudaFuncAttributeMaxDynamicSharedMemorySize, MM_SMEM);
    cudaFuncSetAttribute(attn_kernel, cudaFuncAttributeMaxDynamicSharedMemorySize,
                         SM_TOT * (int)sizeof(float));

    split_x_kernel<<<NROWS * CDIM / 4 / 256, 256>>>(x);
    split_w_kernel<<<dim3(H * CDIM / 256, 3), 256>>>(Wq, Wk, Wv);
    mm_kernel<<<dim3(NROWS / 128, 3), 256, MM_SMEM>>>();
    attn_kernel<<<dim3(T / AQ, B), 256, SM_TOT * sizeof(float)>>>(out);
}

// round 8
// speedup vs baseline: 2.8490x; 2.1456x over previous
#include <cuda_runtime.h>
#include <cuda_bf16.h>
#include <cstdint>
#include <math.h>

#define B 4
#define T 4096
#define CDIM 2048
#define H 128
#define NROWS (B*T)

// Scratch (device globals per harness rules)
__device__ __nv_bfloat16 g_xh[NROWS*CDIM];     // x hi split
__device__ __nv_bfloat16 g_xl[NROWS*CDIM];     // x lo split
__device__ __nv_bfloat16 g_Wh[3*H*CDIM];       // W packed [w][n][k] hi
__device__ __nv_bfloat16 g_Wl[3*H*CDIM];       // W packed [w][n][k] lo
__device__ __nv_bfloat16 g_Qh[NROWS*H];        // Q (scaled) hi  [row][d]
__device__ __nv_bfloat16 g_Ql[NROWS*H];
__device__ __nv_bfloat16 g_Kh[NROWS*H];        // K hi [row][d]
__device__ __nv_bfloat16 g_Kl[NROWS*H];
__device__ __nv_bfloat16 g_Vth[H*NROWS];       // V^T hi [d][row]
__device__ __nv_bfloat16 g_Vtl[H*NROWS];

__device__ __forceinline__ uint32_t smem_u32(const void* p) {
    uint32_t a;
    asm("{ .reg .u64 t; cvta.to.shared.u64 t, %1; cvt.u32.u64 %0, t; }" : "=r"(a) : "l"(p));
    return a;
}

__device__ __forceinline__ void cp_async16(uint32_t dst, const void* src) {
    asm volatile("cp.async.cg.shared.global [%0], [%1], 16;" :: "r"(dst), "l"(src) : "memory");
}
#define CP_COMMIT() asm volatile("cp.async.commit_group;" ::: "memory")
#define CP_WAIT1()  asm volatile("cp.async.wait_group 1;" ::: "memory")
#define CP_WAIT0()  asm volatile("cp.async.wait_group 0;" ::: "memory")

__device__ __forceinline__ void ldsm4(uint32_t addr, uint32_t* r) {
    asm volatile("ldmatrix.sync.aligned.m8n8.x4.shared.b16 {%0,%1,%2,%3}, [%4];"
        : "=r"(r[0]), "=r"(r[1]), "=r"(r[2]), "=r"(r[3]) : "r"(addr));
}

__device__ __forceinline__ void mma16816(float* c, const uint32_t* a, uint32_t b0, uint32_t b1) {
    asm volatile("mma.sync.aligned.m16n8k16.row.col.f32.bf16.bf16.f32 "
        "{%0,%1,%2,%3}, {%4,%5,%6,%7}, {%8,%9}, {%0,%1,%2,%3};"
        : "+f"(c[0]), "+f"(c[1]), "+f"(c[2]), "+f"(c[3])
        : "r"(a[0]), "r"(a[1]), "r"(a[2]), "r"(a[3]), "r"(b0), "r"(b1));
}

// Fast exp2 in the FMA pipe (no MUFU): Schraudolph round + deg-5 Taylor.
// Valid for x <= 0; clamps below -100 -> ~0. Rel err ~4e-6.
__device__ __forceinline__ float exp2p(float x) {
    x = fmaxf(x, -100.f);
    float t = x + 12582912.f;                       // 1.5*2^23: round-to-int in mantissa
    int k = __float_as_int(t) - 0x4B400000;         // = round(x)
    float f = x - (t - 12582912.f);                 // f in [-0.5, 0.5]
    float r = 0.00133336f;
    r = fmaf(r, f, 0.00961813f);
    r = fmaf(r, f, 0.05550411f);
    r = fmaf(r, f, 0.24022651f);
    r = fmaf(r, f, 0.69314718f);
    r = fmaf(r, f, 1.0f);
    return __int_as_float(__float_as_int(r) + (k << 23));
}

// pack two floats into bf16x2 hi, return residual bf16x2 lo via out-param
__device__ __forceinline__ uint32_t pack_hl(float a, float b, uint32_t& lo) {
    __nv_bfloat16 ha = __float2bfloat16_rn(a), hb = __float2bfloat16_rn(b);
    __nv_bfloat16 la = __float2bfloat16_rn(a - __bfloat162float(ha));
    __nv_bfloat16 lb = __float2bfloat16_rn(b - __bfloat162float(hb));
    __nv_bfloat162 h2 = __halves2bfloat162(ha, hb);
    __nv_bfloat162 l2 = __halves2bfloat162(la, lb);
    lo = *reinterpret_cast<uint32_t*>(&l2);
    return *reinterpret_cast<uint32_t*>(&h2);
}

// ============================================================
// Split kernels: fp32 -> bf16 hi + lo
// ============================================================
__global__ __launch_bounds__(256) void split_x_kernel(const float* __restrict__ x)
{
    int i = blockIdx.x * 256 + threadIdx.x;   // float4 index
    float4 v = ((const float4*)x)[i];
    __nv_bfloat16 h0 = __float2bfloat16_rn(v.x);
    __nv_bfloat16 h1 = __float2bfloat16_rn(v.y);
    __nv_bfloat16 h2 = __float2bfloat16_rn(v.z);
    __nv_bfloat16 h3 = __float2bfloat16_rn(v.w);
    __nv_bfloat16 l0 = __float2bfloat16_rn(v.x - __bfloat162float(h0));
    __nv_bfloat16 l1 = __float2bfloat16_rn(v.y - __bfloat162float(h1));
    __nv_bfloat16 l2 = __float2bfloat16_rn(v.z - __bfloat162float(h2));
    __nv_bfloat16 l3 = __float2bfloat16_rn(v.w - __bfloat162float(h3));
    __nv_bfloat162* ph = (__nv_bfloat162*)g_xh;
    __nv_bfloat162* pl = (__nv_bfloat162*)g_xl;
    ph[2*i]   = __halves2bfloat162(h0, h1);
    ph[2*i+1] = __halves2bfloat162(h2, h3);
    pl[2*i]   = __halves2bfloat162(l0, l1);
    pl[2*i+1] = __halves2bfloat162(l2, l3);
}

__global__ __launch_bounds__(256) void split_w_kernel(const float* __restrict__ Wq,
                                                      const float* __restrict__ Wk,
                                                      const float* __restrict__ Wv)
{
    int w = blockIdx.y;
    const float* W = (w == 0) ? Wq : (w == 1) ? Wk : Wv;
    int idx = blockIdx.x * 256 + threadIdx.x;   // n*2048 + k
    int n = idx >> 11;
    int k = idx & 2047;
    float v = W[(size_t)k * H + n];
    __nv_bfloat16 h = __float2bfloat16_rn(v);
    __nv_bfloat16 l = __float2bfloat16_rn(v - __bfloat162float(h));
    g_Wh[(size_t)w * H * CDIM + idx] = h;
    g_Wl[(size_t)w * H * CDIM + idx] = l;
}

// ============================================================
// HMMA projection GEMM (core verified R7). Epilogue now writes bf16 hi/lo
// attention operands: Q scaled by 2048^-.05*log2e; V transposed [d][row].
// ============================================================
#define KC 32
#define NITER (CDIM / KC)
#define RSB 80
#define MAT_B (128 * RSB)
#define STAGE_B (4 * MAT_B)
#define NSTAGE 3
#define MM_SMEM (NSTAGE * STAGE_B)

__global__ __launch_bounds__(256, 1)
void mm_kernel()
{
    extern __shared__ char dsm[];
    uint32_t sb = smem_u32(dsm);
    int tid = threadIdx.x;
    int lid = tid & 31, wid = tid >> 5;
    int wm = wid & 3, wn = wid >> 2;
    int mBase = blockIdx.x * 128;
    int wsel  = blockIdx.y;
    int nBase = wsel * 128;

    int r0 = tid >> 2, c0 = (tid & 3);
    int r1 = (tid + 256) >> 2, c1 = (tid & 3);

    float acc[2][8][4];
    #pragma unroll
    for (int mt = 0; mt < 2; mt++)
        #pragma unroll
        for (int nt = 0; nt < 8; nt++)
            #pragma unroll
            for (int e = 0; e < 4; e++) acc[mt][nt][e] = 0.f;

    auto load_stage = [&](int stage, int k0) {
        uint32_t s = sb + stage * STAGE_B;
        const __nv_bfloat16* xh = g_xh + (size_t)(mBase + r0) * CDIM + k0 + c0 * 8;
        const __nv_bfloat16* xl = g_xl + (size_t)(mBase + r0) * CDIM + k0 + c0 * 8;
        const __nv_bfloat16* wh = g_Wh + (size_t)(nBase + r0) * CDIM + k0 + c0 * 8;
        const __nv_bfloat16* wl = g_Wl + (size_t)(nBase + r0) * CDIM + k0 + c0 * 8;
        uint32_t d = s + r0 * RSB + c0 * 16;
        cp_async16(d + 0*MAT_B, xh);
        cp_async16(d + 1*MAT_B, xl);
        cp_async16(d + 2*MAT_B, wh);
        cp_async16(d + 3*MAT_B, wl);
        xh = g_xh + (size_t)(mBase + r1) * CDIM + k0 + c1 * 8;
        xl = g_xl + (size_t)(mBase + r1) * CDIM + k0 + c1 * 8;
        wh = g_Wh + (size_t)(nBase + r1) * CDIM + k0 + c1 * 8;
        wl = g_Wl + (size_t)(nBase + r1) * CDIM + k0 + c1 * 8;
        d = s + r1 * RSB + c1 * 16;
        cp_async16(d + 0*MAT_B, xh);
        cp_async16(d + 1*MAT_B, xl);
        cp_async16(d + 2*MAT_B, wh);
        cp_async16(d + 3*MAT_B, wl);
    };

    load_stage(0, 0);  CP_COMMIT();
    load_stage(1, KC); CP_COMMIT();

    int lrow = lid & 15, lkh = lid >> 4;

    for (int it = 0; it < NITER; it++) {
        CP_WAIT1();
        __syncthreads();
        if (it + 2 < NITER) load_stage((it + 2) % NSTAGE, (it + 2) * KC);
        CP_COMMIT();

        uint32_t s = sb + (it % NSTAGE) * STAGE_B;
        #pragma unroll
        for (int ks = 0; ks < 2; ks++) {
            uint32_t kOff = ks * 32 + lkh * 16;
            uint32_t a_hi[2][4], a_lo[2][4];
            #pragma unroll
            for (int mt = 0; mt < 2; mt++) {
                uint32_t ra = (wm * 32 + mt * 16 + lrow) * RSB + kOff;
                ldsm4(s + 0*MAT_B + ra, a_hi[mt]);
                ldsm4(s + 1*MAT_B + ra, a_lo[mt]);
            }
            uint32_t b_hi[4][4], b_lo[4][4];
            #pragma unroll
            for (int j = 0; j < 4; j++) {
                uint32_t rb = (wn * 64 + j * 16 + lrow) * RSB + kOff;
                ldsm4(s + 2*MAT_B + rb, b_hi[j]);
                ldsm4(s + 3*MAT_B + rb, b_lo[j]);
            }
            #pragma unroll
            for (int mt = 0; mt < 2; mt++)
                #pragma unroll
                for (int nt = 0; nt < 8; nt++) {
                    int j = nt >> 1, sel = nt & 1;
                    uint32_t bh0 = b_hi[j][sel], bh1 = b_hi[j][sel + 2];
                    uint32_t bl0 = b_lo[j][sel], bl1 = b_lo[j][sel + 2];
                    mma16816(acc[mt][nt], a_hi[mt], bh0, bh1);
                    mma16816(acc[mt][nt], a_hi[mt], bl0, bl1);
                    mma16816(acc[mt][nt], a_lo[mt], bh0, bh1);
                }
        }
        __syncthreads();
    }

    // Epilogue: bf16 hi/lo operands for attention
    const float F = (wsel == 0) ? (powf(2048.0f, -0.05f) * 1.44269504089f) : 1.0f;
    #pragma unroll
    for (int mt = 0; mt < 2; mt++)
        #pragma unroll
        for (int nt = 0; nt < 8; nt++) {
            int row = mBase + wm * 32 + mt * 16 + (lid >> 2);
            int col = wn * 64 + nt * 8 + 2 * (lid & 3);
            float v0 = acc[mt][nt][0] * F, v1 = acc[mt][nt][1] * F;
            float v2 = acc[mt][nt][2] * F, v3 = acc[mt][nt][3] * F;
            if (wsel < 2) {
                __nv_bfloat16* oh = (wsel == 0) ? g_Qh : g_Kh;
                __nv_bfloat16* ol = (wsel == 0) ? g_Ql : g_Kl;
                uint32_t lo01, lo23;
                uint32_t hi01 = pack_hl(v0, v1, lo01);
                uint32_t hi23 = pack_hl(v2, v3, lo23);
                *(uint32_t*)&oh[(size_t)row * H + col]       = hi01;
                *(uint32_t*)&ol[(size_t)row * H + col]       = lo01;
                *(uint32_t*)&oh[(size_t)(row + 8) * H + col] = hi23;
                *(uint32_t*)&ol[(size_t)(row + 8) * H + col] = lo23;
            } else {
                // V transposed: Vt[d][row]
                __nv_bfloat16 h0 = __float2bfloat16_rn(v0);
                __nv_bfloat16 h1 = __float2bfloat16_rn(v1);
                __nv_bfloat16 h2 = __float2bfloat16_rn(v2);
                __nv_bfloat16 h3 = __float2bfloat16_rn(v3);
                g_Vth[(size_t)col       * NROWS + row]     = h0;
                g_Vth[(size_t)(col + 1) * NROWS + row]     = h1;
                g_Vth[(size_t)col       * NROWS + row + 8] = h2;
                g_Vth[(size_t)(col + 1) * NROWS + row + 8] = h3;
                g_Vtl[(size_t)col       * NROWS + row]     = __float2bfloat16_rn(v0 - __bfloat162float(h0));
                g_Vtl[(size_t)(col + 1) * NROWS + row]     = __float2bfloat16_rn(v1 - __bfloat162float(h1));
                g_Vtl[(size_t)col       * NROWS + row + 8] = __float2bfloat16_rn(v2 - __bfloat162float(h2));
                g_Vtl[(size_t)(col + 1) * NROWS + row + 8] = __float2bfloat16_rn(v3 - __bfloat162float(h3));
            }
        }
}

// ============================================================
// HMMA flash attention: BQ=128 (8 warps x m16), BKV=64, 2-stage cp.async.
// S = Qh*Kh + Qh*Kl + Ql*Kh ; P hi/lo repacked from S frags ; O = Ph*Vh + Ph*Vl + Pl*Vh.
// exp via FMA-pipe exp2 poly (base-2 folded into Q scale).
// ============================================================
#define QROWB 272                     // 128 bf16 + 16B pad
#define AKROWB 272
#define AVROWB 144                    // 64 bf16 + 16B pad
#define AQ_OFF_H 0
#define AQ_OFF_L (128 * QROWB)        // 34816
#define AQ_BYTES (2 * 128 * QROWB)    // 69632
#define KH_OFF 0
#define KL_OFF (64 * AKROWB)          // 17408
#define VTH_OFF (2 * 64 * AKROWB)     // 34816
#define VTL_OFF (VTH_OFF + 128 * AVROWB)  // 53248
#define ASTAGE_B (VTL_OFF + 128 * AVROWB) // 71680
#define ATT_SMEM (AQ_BYTES + 2 * ASTAGE_B) // 212992

__global__ __launch_bounds__(256, 1)
void attn_kernel(float* __restrict__ out)
{
    extern __shared__ char dsm[];
    uint32_t sb = smem_u32(dsm);
    int tid = threadIdx.x;
    int lid = tid & 31, wid = tid >> 5;
    int lrow = lid & 15, lkh = lid >> 4;
    int r4 = lid >> 2, c2 = 2 * (lid & 3);
    int b = blockIdx.y;
    int qTile = 31 - (int)blockIdx.x;           // big tiles first
    int qBase = qTile * 128;
    int bT = b * T;
    int nChunks = 2 * qTile + 2;
    int qw = qBase + wid * 16;                  // warp's first q row

    // ---- load Q (hi+lo) ----
    #pragma unroll
    for (int t = 0; t < 8; t++) {
        int idx = tid + t * 256;                // 0..2047
        int row = idx >> 4, c16 = idx & 15;
        uint32_t d = sb + AQ_OFF_H + row * QROWB + c16 * 16;
        cp_async16(d, g_Qh + (size_t)(bT + qBase + row) * H + c16 * 8);
        cp_async16(d + AQ_OFF_L, g_Ql + (size_t)(bT + qBase + row) * H + c16 * 8);
    }

    auto load_kv = [&](int c) {
        uint32_t stg = sb + AQ_BYTES + (c & 1) * ASTAGE_B;
        int kvB = c * 64;
        #pragma unroll
        for (int t = 0; t < 4; t++) {
            int idx = tid + t * 256;            // 0..1023
            int row = idx >> 4, c16 = idx & 15; // K: 64 rows x 16 chunks
            uint32_t d = stg + row * AKROWB + c16 * 16;
            const __nv_bfloat16* src = g_Kh + (size_t)(bT + kvB + row) * H + c16 * 8;
            cp_async16(d + KH_OFF, src);
            cp_async16(d + KL_OFF, g_Kl + (size_t)(bT + kvB + row) * H + c16 * 8);
            int vrow = idx >> 3, vc16 = idx & 7; // Vt: 128 rows x 8 chunks
            uint32_t dv = stg + vrow * AVROWB + vc16 * 16;
            cp_async16(dv + VTH_OFF, g_Vth + (size_t)vrow * NROWS + bT + kvB + vc16 * 8);
            cp_async16(dv + VTL_OFF, g_Vtl + (size_t)vrow * NROWS + bT + kvB + vc16 * 8);
        }
    };

    load_kv(0);
    CP_COMMIT();

    float O[16][4];
    #pragma unroll
    for (int nt = 0; nt < 16; nt++)
        #pragma unroll
        for (int e = 0; e < 4; e++) O[nt][e] = 0.f;
    float m0 = -1e30f, m1 = -1e30f, l0 = 0.f, l1 = 0.f;

    for (int c = 0; c < nChunks; c++) {
        CP_WAIT0();
        __syncthreads();
        if (c + 1 < nChunks) load_kv(c + 1);
        CP_COMMIT();

        int kvBase = c * 64;
        if (kvBase <= qw + 15) {                // warp has unmasked work in this chunk
            uint32_t stg = sb + AQ_BYTES + (c & 1) * ASTAGE_B;

            // ---- S = Q K^T (3-way split) ----
            float sf[8][4];
            #pragma unroll
            for (int j = 0; j < 8; j++)
                #pragma unroll
                for (int e = 0; e < 4; e++) sf[j][e] = 0.f;

            uint32_t qa = sb + AQ_OFF_H + (wid * 16 + lrow) * QROWB + lkh * 16;
            #pragma unroll
            for (int k8 = 0; k8 < 8; k8++) {
                uint32_t ah[4], al[4];
                ldsm4(qa + k8 * 32, ah);
                ldsm4(qa + k8 * 32 + AQ_OFF_L, al);
                #pragma unroll
                for (int j4 = 0; j4 < 4; j4++) {
                    uint32_t ka = stg + (j4 * 16 + lrow) * AKROWB + k8 * 32 + lkh * 16;
                    uint32_t bh[4], bl[4];
                    ldsm4(ka + KH_OFF, bh);
                    ldsm4(ka + KL_OFF, bl);
                    #pragma unroll
                    for (int sel = 0; sel < 2; sel++) {
                        float* s8 = sf[j4 * 2 + sel];
                        mma16816(s8, ah, bh[sel], bh[sel + 2]);
                        mma16816(s8, ah, bl[sel], bl[sel + 2]);
                        mma16816(s8, al, bh[sel], bh[sel + 2]);
                    }
                }
            }

            // ---- causal mask (diagonal chunks only) ----
            if (kvBase + 63 > qw) {
                int q0 = qw + r4, q1 = q0 + 8;
                #pragma unroll
                for (int j = 0; j < 8; j++) {
                    int kvc = kvBase + j * 8 + c2;
                    if (kvc     > q0) sf[j][0] = -1e30f;
                    if (kvc + 1 > q0) sf[j][1] = -1e30f;
                    if (kvc     > q1) sf[j][2] = -1e30f;
                    if (kvc + 1 > q1) sf[j][3] = -1e30f;
                }
            }

            // ---- online softmax (base-2; scale folded into Q) ----
            float mx0 = -1e30f, mx1 = -1e30f;
            #pragma unroll
            for (int j = 0; j < 8; j++) {
                mx0 = fmaxf(mx0, fmaxf(sf[j][0], sf[j][1]));
                mx1 = fmaxf(mx1, fmaxf(sf[j][2], sf[j][3]));
            }
            mx0 = fmaxf(mx0, __shfl_xor_sync(0xffffffffu, mx0, 1));
            mx0 = fmaxf(mx0, __shfl_xor_sync(0xffffffffu, mx0, 2));
            mx1 = fmaxf(mx1, __shfl_xor_sync(0xffffffffu, mx1, 1));
            mx1 = fmaxf(mx1, __shfl_xor_sync(0xffffffffu, mx1, 2));
            float mn0 = fmaxf(m0, mx0), mn1 = fmaxf(m1, mx1);
            float sc0 = exp2p(m0 - mn0), sc1 = exp2p(m1 - mn1);
            float sum0 = 0.f, sum1 = 0.f;
            #pragma unroll
            for (int j = 0; j < 8; j++) {
                sf[j][0] = exp2p(sf[j][0] - mn0); sum0 += sf[j][0];
                sf[j][1] = exp2p(sf[j][1] - mn0); sum0 += sf[j][1];
                sf[j][2] = exp2p(sf[j][2] - mn1); sum1 += sf[j][2];
                sf[j][3] = exp2p(sf[j][3] - mn1); sum1 += sf[j][3];
            }
            sum0 += __shfl_xor_sync(0xffffffffu, sum0, 1);
            sum0 += __shfl_xor_sync(0xffffffffu, sum0, 2);
            sum1 += __shfl_xor_sync(0xffffffffu, sum1, 1);
            sum1 += __shfl_xor_sync(0xffffffffu, sum1, 2);
            l0 = l0 * sc0 + sum0;
            l1 = l1 * sc1 + sum1;
            m0 = mn0; m1 = mn1;
            #pragma unroll
            for (int nt = 0; nt < 16; nt++) {
                O[nt][0] *= sc0; O[nt][1] *= sc0;
                O[nt][2] *= sc1; O[nt][3] *= sc1;
            }

            // ---- O += P V (P repacked from S frags, 3-way split) ----
            #pragma unroll
            for (int kk = 0; kk < 4; kk++) {
                uint32_t ph[4], pl[4];
                ph[0] = pack_hl(sf[2*kk][0],   sf[2*kk][1],   pl[0]);
                ph[1] = pack_hl(sf[2*kk][2],   sf[2*kk][3],   pl[1]);
                ph[2] = pack_hl(sf[2*kk+1][0], sf[2*kk+1][1], pl[2]);
                ph[3] = pack_hl(sf[2*kk+1][2], sf[2*kk+1][3], pl[3]);
                #pragma unroll
                for (int t = 0; t < 8; t++) {
                    uint32_t va = stg + (t * 16 + lrow) * AVROWB + kk * 32 + lkh * 16;
                    uint32_t vh[4], vl[4];
                    ldsm4(va + VTH_OFF, vh);
                    ldsm4(va + VTL_OFF, vl);
                    float* o0 = O[2*t];
                    float* o1 = O[2*t + 1];
                    mma16816(o0, ph, vh[0], vh[2]);
                    mma16816(o0, ph, vl[0], vl[2]);
                    mma16816(o0, pl, vh[0], vh[2]);
                    mma16816(o1, ph, vh[1], vh[3]);
                    mma16816(o1, ph, vl[1], vl[3]);
                    mma16816(o1, pl, vh[1], vh[3]);
                }
            }
        }
    }

    // ---- epilogue ----
    float inv0 = 1.0f / l0, inv1 = 1.0f / l1;
    size_t row0 = (size_t)(bT + qw + r4) * H;
    size_t row1 = (size_t)(bT + qw + r4 + 8) * H;
    #pragma unroll
    for (int nt = 0; nt < 16; nt++) {
        int col = nt * 8 + c2;
        *(float2*)&out[row0 + col] = make_float2(O[nt][0] * inv0, O[nt][1] * inv0);
        *(float2*)&out[row1 + col] = make_float2(O[nt][2] * inv1, O[nt][3] * inv1);
    }
}

extern "C" void kernel_launch(void* const* d_in, const int* in_sizes, int n_in,
                              void* d_out, int out_size)
{
    const float* x  = (const float*)d_in[0];
    const float* Wq = (const float*)d_in[1];
    const float* Wk = (const float*)d_in[2];
    const float* Wv = (const float*)d_in[3];
    float* out = (float*)d_out;

    cudaFuncSetAttribute(mm_kernel, cudaFuncAttributeMaxDynamicSharedMemorySize, MM_SMEM);
    cudaFuncSetAttribute(attn_kernel, cudaFuncAttributeMaxDynamicSharedMemorySize, ATT_SMEM);

    split_x_kernel<<<NROWS * CDIM / 4 / 256, 256>>>(x);
    split_w_kernel<<<dim3(H * CDIM / 256, 3), 256>>>(Wq, Wk, Wv);
    mm_kernel<<<dim3(NROWS / 128, 3), 256, MM_SMEM>>>();
    attn_kernel<<<dim3(T / 128, B), 256, ATT_SMEM>>>(out);
}

// round 9
// speedup vs baseline: 3.6220x; 1.2713x over previous
#include <cuda_runtime.h>
#include <cuda_bf16.h>
#include <cstdint>
#include <math.h>

#define B 4
#define T 4096
#define CDIM 2048
#define H 128
#define NROWS (B*T)

// Scratch (device globals per harness rules)
__device__ __nv_bfloat16 g_xh[NROWS*CDIM];     // x hi split
__device__ __nv_bfloat16 g_xl[NROWS*CDIM];     // x lo split
__device__ __nv_bfloat16 g_Wh[3*H*CDIM];       // W packed [w][n][k] hi
__device__ __nv_bfloat16 g_Wl[3*H*CDIM];       // W packed [w][n][k] lo
__device__ __nv_bfloat16 g_Qh[NROWS*H];        // Q (scaled) hi  [row][d]
__device__ __nv_bfloat16 g_Ql[NROWS*H];
__device__ __nv_bfloat16 g_Kh[NROWS*H];        // K hi [row][d]
__device__ __nv_bfloat16 g_Kl[NROWS*H];
__device__ __nv_bfloat16 g_Vth[H*NROWS];       // V^T hi [d][row]
__device__ __nv_bfloat16 g_Vtl[H*NROWS];
// flash-decoding partials: up to 4 KV segments per q-tile
__device__ float g_Op[4][NROWS*H];             // unnormalized partial O
__device__ float g_ml[2][4][NROWS];            // [0]=m, [1]=l per row per segment

__device__ __forceinline__ uint32_t smem_u32(const void* p) {
    uint32_t a;
    asm("{ .reg .u64 t; cvta.to.shared.u64 t, %1; cvt.u32.u64 %0, t; }" : "=r"(a) : "l"(p));
    return a;
}

__device__ __forceinline__ void cp_async16(uint32_t dst, const void* src) {
    asm volatile("cp.async.cg.shared.global [%0], [%1], 16;" :: "r"(dst), "l"(src) : "memory");
}
#define CP_COMMIT() asm volatile("cp.async.commit_group;" ::: "memory")
#define CP_WAIT1()  asm volatile("cp.async.wait_group 1;" ::: "memory")
#define CP_WAIT0()  asm volatile("cp.async.wait_group 0;" ::: "memory")

__device__ __forceinline__ void ldsm4(uint32_t addr, uint32_t* r) {
    asm volatile("ldmatrix.sync.aligned.m8n8.x4.shared.b16 {%0,%1,%2,%3}, [%4];"
        : "=r"(r[0]), "=r"(r[1]), "=r"(r[2]), "=r"(r[3]) : "r"(addr));
}

__device__ __forceinline__ void mma16816(float* c, const uint32_t* a, uint32_t b0, uint32_t b1) {
    asm volatile("mma.sync.aligned.m16n8k16.row.col.f32.bf16.bf16.f32 "
        "{%0,%1,%2,%3}, {%4,%5,%6,%7}, {%8,%9}, {%0,%1,%2,%3};"
        : "+f"(c[0]), "+f"(c[1]), "+f"(c[2]), "+f"(c[3])
        : "r"(a[0]), "r"(a[1]), "r"(a[2]), "r"(a[3]), "r"(b0), "r"(b1));
}

// Fast exp2 in the FMA pipe (no MUFU): Schraudolph round + deg-5 Taylor.
__device__ __forceinline__ float exp2p(float x) {
    x = fmaxf(x, -100.f);
    float t = x + 12582912.f;
    int k = __float_as_int(t) - 0x4B400000;
    float f = x - (t - 12582912.f);
    float r = 0.00133336f;
    r = fmaf(r, f, 0.00961813f);
    r = fmaf(r, f, 0.05550411f);
    r = fmaf(r, f, 0.24022651f);
    r = fmaf(r, f, 0.69314718f);
    r = fmaf(r, f, 1.0f);
    return __int_as_float(__float_as_int(r) + (k << 23));
}

__device__ __forceinline__ uint32_t pack_hl(float a, float b, uint32_t& lo) {
    __nv_bfloat16 ha = __float2bfloat16_rn(a), hb = __float2bfloat16_rn(b);
    __nv_bfloat16 la = __float2bfloat16_rn(a - __bfloat162float(ha));
    __nv_bfloat16 lb = __float2bfloat16_rn(b - __bfloat162float(hb));
    __nv_bfloat162 h2 = __halves2bfloat162(ha, hb);
    __nv_bfloat162 l2 = __halves2bfloat162(la, lb);
    lo = *reinterpret_cast<uint32_t*>(&l2);
    return *reinterpret_cast<uint32_t*>(&h2);
}

// ============================================================
// Split kernels: fp32 -> bf16 hi + lo
// ============================================================
__global__ __launch_bounds__(256) void split_x_kernel(const float* __restrict__ x)
{
    int i = blockIdx.x * 256 + threadIdx.x;
    float4 v = ((const float4*)x)[i];
    __nv_bfloat16 h0 = __float2bfloat16_rn(v.x);
    __nv_bfloat16 h1 = __float2bfloat16_rn(v.y);
    __nv_bfloat16 h2 = __float2bfloat16_rn(v.z);
    __nv_bfloat16 h3 = __float2bfloat16_rn(v.w);
    __nv_bfloat16 l0 = __float2bfloat16_rn(v.x - __bfloat162float(h0));
    __nv_bfloat16 l1 = __float2bfloat16_rn(v.y - __bfloat162float(h1));
    __nv_bfloat16 l2 = __float2bfloat16_rn(v.z - __bfloat162float(h2));
    __nv_bfloat16 l3 = __float2bfloat16_rn(v.w - __bfloat162float(h3));
    __nv_bfloat162* ph = (__nv_bfloat162*)g_xh;
    __nv_bfloat162* pl = (__nv_bfloat162*)g_xl;
    ph[2*i]   = __halves2bfloat162(h0, h1);
    ph[2*i+1] = __halves2bfloat162(h2, h3);
    pl[2*i]   = __halves2bfloat162(l0, l1);
    pl[2*i+1] = __halves2bfloat162(l2, l3);
}

__global__ __launch_bounds__(256) void split_w_kernel(const float* __restrict__ Wq,
                                                      const float* __restrict__ Wk,
                                                      const float* __restrict__ Wv)
{
    int w = blockIdx.y;
    const float* W = (w == 0) ? Wq : (w == 1) ? Wk : Wv;
    int idx = blockIdx.x * 256 + threadIdx.x;
    int n = idx >> 11;
    int k = idx & 2047;
    float v = W[(size_t)k * H + n];
    __nv_bfloat16 h = __float2bfloat16_rn(v);
    __nv_bfloat16 l = __float2bfloat16_rn(v - __bfloat162float(h));
    g_Wh[(size_t)w * H * CDIM + idx] = h;
    g_Wl[(size_t)w * H * CDIM + idx] = l;
}

// ============================================================
// HMMA projection GEMM (verified R8). Writes bf16 hi/lo attention operands.
// ============================================================
#define KC 32
#define NITER (CDIM / KC)
#define RSB 80
#define MAT_B (128 * RSB)
#define STAGE_B (4 * MAT_B)
#define NSTAGE 3
#define MM_SMEM (NSTAGE * STAGE_B)

__global__ __launch_bounds__(256, 1)
void mm_kernel()
{
    extern __shared__ char dsm[];
    uint32_t sb = smem_u32(dsm);
    int tid = threadIdx.x;
    int lid = tid & 31, wid = tid >> 5;
    int wm = wid & 3, wn = wid >> 2;
    int mBase = blockIdx.x * 128;
    int wsel  = blockIdx.y;
    int nBase = wsel * 128;

    int r0 = tid >> 2, c0 = (tid & 3);
    int r1 = (tid + 256) >> 2, c1 = (tid & 3);

    float acc[2][8][4];
    #pragma unroll
    for (int mt = 0; mt < 2; mt++)
        #pragma unroll
        for (int nt = 0; nt < 8; nt++)
            #pragma unroll
            for (int e = 0; e < 4; e++) acc[mt][nt][e] = 0.f;

    auto load_stage = [&](int stage, int k0) {
        uint32_t s = sb + stage * STAGE_B;
        const __nv_bfloat16* xh = g_xh + (size_t)(mBase + r0) * CDIM + k0 + c0 * 8;
        const __nv_bfloat16* xl = g_xl + (size_t)(mBase + r0) * CDIM + k0 + c0 * 8;
        const __nv_bfloat16* wh = g_Wh + (size_t)(nBase + r0) * CDIM + k0 + c0 * 8;
        const __nv_bfloat16* wl = g_Wl + (size_t)(nBase + r0) * CDIM + k0 + c0 * 8;
        uint32_t d = s + r0 * RSB + c0 * 16;
        cp_async16(d + 0*MAT_B, xh);
        cp_async16(d + 1*MAT_B, xl);
        cp_async16(d + 2*MAT_B, wh);
        cp_async16(d + 3*MAT_B, wl);
        xh = g_xh + (size_t)(mBase + r1) * CDIM + k0 + c1 * 8;
        xl = g_xl + (size_t)(mBase + r1) * CDIM + k0 + c1 * 8;
        wh = g_Wh + (size_t)(nBase + r1) * CDIM + k0 + c1 * 8;
        wl = g_Wl + (size_t)(nBase + r1) * CDIM + k0 + c1 * 8;
        d = s + r1 * RSB + c1 * 16;
        cp_async16(d + 0*MAT_B, xh);
        cp_async16(d + 1*MAT_B, xl);
        cp_async16(d + 2*MAT_B, wh);
        cp_async16(d + 3*MAT_B, wl);
    };

    load_stage(0, 0);  CP_COMMIT();
    load_stage(1, KC); CP_COMMIT();

    int lrow = lid & 15, lkh = lid >> 4;

    for (int it = 0; it < NITER; it++) {
        CP_WAIT1();
        __syncthreads();
        if (it + 2 < NITER) load_stage((it + 2) % NSTAGE, (it + 2) * KC);
        CP_COMMIT();

        uint32_t s = sb + (it % NSTAGE) * STAGE_B;
        #pragma unroll
        for (int ks = 0; ks < 2; ks++) {
            uint32_t kOff = ks * 32 + lkh * 16;
            uint32_t a_hi[2][4], a_lo[2][4];
            #pragma unroll
            for (int mt = 0; mt < 2; mt++) {
                uint32_t ra = (wm * 32 + mt * 16 + lrow) * RSB + kOff;
                ldsm4(s + 0*MAT_B + ra, a_hi[mt]);
                ldsm4(s + 1*MAT_B + ra, a_lo[mt]);
            }
            uint32_t b_hi[4][4], b_lo[4][4];
            #pragma unroll
            for (int j = 0; j < 4; j++) {
                uint32_t rb = (wn * 64 + j * 16 + lrow) * RSB + kOff;
                ldsm4(s + 2*MAT_B + rb, b_hi[j]);
                ldsm4(s + 3*MAT_B + rb, b_lo[j]);
            }
            #pragma unroll
            for (int mt = 0; mt < 2; mt++)
                #pragma unroll
                for (int nt = 0; nt < 8; nt++) {
                    int j = nt >> 1, sel = nt & 1;
                    uint32_t bh0 = b_hi[j][sel], bh1 = b_hi[j][sel + 2];
                    uint32_t bl0 = b_lo[j][sel], bl1 = b_lo[j][sel + 2];
                    mma16816(acc[mt][nt], a_hi[mt], bh0, bh1);
                    mma16816(acc[mt][nt], a_hi[mt], bl0, bl1);
                    mma16816(acc[mt][nt], a_lo[mt], bh0, bh1);
                }
        }
        __syncthreads();
    }

    const float F = (wsel == 0) ? (powf(2048.0f, -0.05f) * 1.44269504089f) : 1.0f;
    #pragma unroll
    for (int mt = 0; mt < 2; mt++)
        #pragma unroll
        for (int nt = 0; nt < 8; nt++) {
            int row = mBase + wm * 32 + mt * 16 + (lid >> 2);
            int col = wn * 64 + nt * 8 + 2 * (lid & 3);
            float v0 = acc[mt][nt][0] * F, v1 = acc[mt][nt][1] * F;
            float v2 = acc[mt][nt][2] * F, v3 = acc[mt][nt][3] * F;
            if (wsel < 2) {
                __nv_bfloat16* oh = (wsel == 0) ? g_Qh : g_Kh;
                __nv_bfloat16* ol = (wsel == 0) ? g_Ql : g_Kl;
                uint32_t lo01, lo23;
                uint32_t hi01 = pack_hl(v0, v1, lo01);
                uint32_t hi23 = pack_hl(v2, v3, lo23);
                *(uint32_t*)&oh[(size_t)row * H + col]       = hi01;
                *(uint32_t*)&ol[(size_t)row * H + col]       = lo01;
                *(uint32_t*)&oh[(size_t)(row + 8) * H + col] = hi23;
                *(uint32_t*)&ol[(size_t)(row + 8) * H + col] = lo23;
            } else {
                __nv_bfloat16 h0 = __float2bfloat16_rn(v0);
                __nv_bfloat16 h1 = __float2bfloat16_rn(v1);
                __nv_bfloat16 h2 = __float2bfloat16_rn(v2);
                __nv_bfloat16 h3 = __float2bfloat16_rn(v3);
                g_Vth[(size_t)col       * NROWS + row]     = h0;
                g_Vth[(size_t)(col + 1) * NROWS + row]     = h1;
                g_Vth[(size_t)col       * NROWS + row + 8] = h2;
                g_Vth[(size_t)(col + 1) * NROWS + row + 8] = h3;
                g_Vtl[(size_t)col       * NROWS + row]     = __float2bfloat16_rn(v0 - __bfloat162float(h0));
                g_Vtl[(size_t)(col + 1) * NROWS + row]     = __float2bfloat16_rn(v1 - __bfloat162float(h1));
                g_Vtl[(size_t)col       * NROWS + row + 8] = __float2bfloat16_rn(v2 - __bfloat162float(h2));
                g_Vtl[(size_t)(col + 1) * NROWS + row + 8] = __float2bfloat16_rn(v3 - __bfloat162float(h3));
            }
        }
}

// ============================================================
// HMMA flash attention with KV-split (flash-decoding).
// Grid (80, B): blockIdx.x -> (qTile, segment of <=16 KV chunks).
// Writes unnormalized partial O + (m,l) per row; comb_kernel merges.
// ============================================================
#define QROWB 272
#define AKROWB 272
#define AVROWB 144
#define AQ_OFF_H 0
#define AQ_OFF_L (128 * QROWB)
#define AQ_BYTES (2 * 128 * QROWB)
#define KH_OFF 0
#define KL_OFF (64 * AKROWB)
#define VTH_OFF (2 * 64 * AKROWB)
#define VTL_OFF (VTH_OFF + 128 * AVROWB)
#define ASTAGE_B (VTL_OFF + 128 * AVROWB)
#define ATT_SMEM (AQ_BYTES + 2 * ASTAGE_B)
#define SEG 16                      // KV chunks per segment

__global__ __launch_bounds__(256, 1)
void attn_kernel()
{
    extern __shared__ char dsm[];
    uint32_t sb = smem_u32(dsm);
    int tid = threadIdx.x;
    int lid = tid & 31, wid = tid >> 5;
    int lrow = lid & 15, lkh = lid >> 4;
    int r4 = lid >> 2, c2 = 2 * (lid & 3);
    int b = blockIdx.y;

    // blockIdx.x (0..79) -> (qTile, seg). nseg(i) = ceil((2i+2)/16): 1/2/3/4.
    int idx = blockIdx.x, qTile, seg;
    if (idx < 8)       { qTile = idx; seg = 0; }
    else if (idx < 24) { int r = idx - 8;  qTile = 8  + (r >> 1); seg = r & 1; }
    else if (idx < 48) { int r = idx - 24; qTile = 16 + r / 3;    seg = r % 3; }
    else               { int r = idx - 48; qTile = 24 + (r >> 2); seg = r & 3; }

    int qBase = qTile * 128;
    int bT = b * T;
    int cEnd0 = 2 * qTile + 2;
    int cBeg = seg * SEG;
    int cEnd = min(cBeg + SEG, cEnd0);
    int qw = qBase + wid * 16;

    // ---- load Q (hi+lo) ----
    #pragma unroll
    for (int t = 0; t < 8; t++) {
        int l2 = tid + t * 256;
        int row = l2 >> 4, c16 = l2 & 15;
        uint32_t d = sb + AQ_OFF_H + row * QROWB + c16 * 16;
        cp_async16(d, g_Qh + (size_t)(bT + qBase + row) * H + c16 * 8);
        cp_async16(d + AQ_OFF_L, g_Ql + (size_t)(bT + qBase + row) * H + c16 * 8);
    }

    auto load_kv = [&](int c) {
        uint32_t stg = sb + AQ_BYTES + (c & 1) * ASTAGE_B;
        int kvB = c * 64;
        #pragma unroll
        for (int t = 0; t < 4; t++) {
            int l2 = tid + t * 256;
            int row = l2 >> 4, c16 = l2 & 15;
            uint32_t d = stg + row * AKROWB + c16 * 16;
            cp_async16(d + KH_OFF, g_Kh + (size_t)(bT + kvB + row) * H + c16 * 8);
            cp_async16(d + KL_OFF, g_Kl + (size_t)(bT + kvB + row) * H + c16 * 8);
            int vrow = l2 >> 3, vc16 = l2 & 7;
            uint32_t dv = stg + vrow * AVROWB + vc16 * 16;
            cp_async16(dv + VTH_OFF, g_Vth + (size_t)vrow * NROWS + bT + kvB + vc16 * 8);
            cp_async16(dv + VTL_OFF, g_Vtl + (size_t)vrow * NROWS + bT + kvB + vc16 * 8);
        }
    };

    load_kv(cBeg);
    CP_COMMIT();

    float O[16][4];
    #pragma unroll
    for (int nt = 0; nt < 16; nt++)
        #pragma unroll
        for (int e = 0; e < 4; e++) O[nt][e] = 0.f;
    float m0 = -1e30f, m1 = -1e30f, l0 = 0.f, l1 = 0.f;

    for (int c = cBeg; c < cEnd; c++) {
        CP_WAIT0();
        __syncthreads();
        if (c + 1 < cEnd) load_kv(c + 1);
        CP_COMMIT();

        int kvBase = c * 64;
        if (kvBase <= qw + 15) {
            uint32_t stg = sb + AQ_BYTES + (c & 1) * ASTAGE_B;

            float sf[8][4];
            #pragma unroll
            for (int j = 0; j < 8; j++)
                #pragma unroll
                for (int e = 0; e < 4; e++) sf[j][e] = 0.f;

            uint32_t qa = sb + AQ_OFF_H + (wid * 16 + lrow) * QROWB + lkh * 16;
            #pragma unroll
            for (int k8 = 0; k8 < 8; k8++) {
                uint32_t ah[4], al[4];
                ldsm4(qa + k8 * 32, ah);
                ldsm4(qa + k8 * 32 + AQ_OFF_L, al);
                #pragma unroll
                for (int j4 = 0; j4 < 4; j4++) {
                    uint32_t ka = stg + (j4 * 16 + lrow) * AKROWB + k8 * 32 + lkh * 16;
                    uint32_t bh[4], bl[4];
                    ldsm4(ka + KH_OFF, bh);
                    ldsm4(ka + KL_OFF, bl);
                    #pragma unroll
                    for (int sel = 0; sel < 2; sel++) {
                        float* s8 = sf[j4 * 2 + sel];
                        mma16816(s8, ah, bh[sel], bh[sel + 2]);
                        mma16816(s8, ah, bl[sel], bl[sel + 2]);
                        mma16816(s8, al, bh[sel], bh[sel + 2]);
                    }
                }
            }

            if (kvBase + 63 > qw) {
                int q0 = qw + r4, q1 = q0 + 8;
                #pragma unroll
                for (int j = 0; j < 8; j++) {
                    int kvc = kvBase + j * 8 + c2;
                    if (kvc     > q0) sf[j][0] = -1e30f;
                    if (kvc + 1 > q0) sf[j][1] = -1e30f;
                    if (kvc     > q1) sf[j][2] = -1e30f;
                    if (kvc + 1 > q1) sf[j][3] = -1e30f;
                }
            }

            float mx0 = -1e30f, mx1 = -1e30f;
            #pragma unroll
            for (int j = 0; j < 8; j++) {
                mx0 = fmaxf(mx0, fmaxf(sf[j][0], sf[j][1]));
                mx1 = fmaxf(mx1, fmaxf(sf[j][2], sf[j][3]));
            }
            mx0 = fmaxf(mx0, __shfl_xor_sync(0xffffffffu, mx0, 1));
            mx0 = fmaxf(mx0, __shfl_xor_sync(0xffffffffu, mx0, 2));
            mx1 = fmaxf(mx1, __shfl_xor_sync(0xffffffffu, mx1, 1));
            mx1 = fmaxf(mx1, __shfl_xor_sync(0xffffffffu, mx1, 2));
            float mn0 = fmaxf(m0, mx0), mn1 = fmaxf(m1, mx1);
            float sc0 = exp2p(m0 - mn0), sc1 = exp2p(m1 - mn1);
            float sum0 = 0.f, sum1 = 0.f;
            #pragma unroll
            for (int j = 0; j < 8; j++) {
                sf[j][0] = exp2p(sf[j][0] - mn0); sum0 += sf[j][0];
                sf[j][1] = exp2p(sf[j][1] - mn0); sum0 += sf[j][1];
                sf[j][2] = exp2p(sf[j][2] - mn1); sum1 += sf[j][2];
                sf[j][3] = exp2p(sf[j][3] - mn1); sum1 += sf[j][3];
            }
            sum0 += __shfl_xor_sync(0xffffffffu, sum0, 1);
            sum0 += __shfl_xor_sync(0xffffffffu, sum0, 2);
            sum1 += __shfl_xor_sync(0xffffffffu, sum1, 1);
            sum1 += __shfl_xor_sync(0xffffffffu, sum1, 2);
            l0 = l0 * sc0 + sum0;
            l1 = l1 * sc1 + sum1;
            m0 = mn0; m1 = mn1;
            #pragma unroll
            for (int nt = 0; nt < 16; nt++) {
                O[nt][0] *= sc0; O[nt][1] *= sc0;
                O[nt][2] *= sc1; O[nt][3] *= sc1;
            }

            #pragma unroll
            for (int kk = 0; kk < 4; kk++) {
                uint32_t ph[4], pl[4];
                ph[0] = pack_hl(sf[2*kk][0],   sf[2*kk][1],   pl[0]);
                ph[1] = pack_hl(sf[2*kk][2],   sf[2*kk][3],   pl[1]);
                ph[2] = pack_hl(sf[2*kk+1][0], sf[2*kk+1][1], pl[2]);
                ph[3] = pack_hl(sf[2*kk+1][2], sf[2*kk+1][3], pl[3]);
                #pragma unroll
                for (int t = 0; t < 8; t++) {
                    uint32_t va = stg + (t * 16 + lrow) * AVROWB + kk * 32 + lkh * 16;
                    uint32_t vh[4], vl[4];
                    ldsm4(va + VTH_OFF, vh);
                    ldsm4(va + VTL_OFF, vl);
                    float* o0 = O[2*t];
                    float* o1 = O[2*t + 1];
                    mma16816(o0, ph, vh[0], vh[2]);
                    mma16816(o0, ph, vl[0], vl[2]);
                    mma16816(o0, pl, vh[0], vh[2]);
                    mma16816(o1, ph, vh[1], vh[3]);
                    mma16816(o1, ph, vl[1], vl[3]);
                    mma16816(o1, pl, vh[1], vh[3]);
                }
            }
        }
    }

    // ---- epilogue: unnormalized partial O + stats ----
    float* Op = g_Op[seg];
    size_t row0 = (size_t)(bT + qw + r4) * H;
    size_t row1 = (size_t)(bT + qw + r4 + 8) * H;
    #pragma unroll
    for (int nt = 0; nt < 16; nt++) {
        int col = nt * 8 + c2;
        *(float2*)&Op[row0 + col] = make_float2(O[nt][0], O[nt][1]);
        *(float2*)&Op[row1 + col] = make_float2(O[nt][2], O[nt][3]);
    }
    if ((lid & 3) == 0) {
        g_ml[0][seg][bT + qw + r4]     = m0;
        g_ml[1][seg][bT + qw + r4]     = l0;
        g_ml[0][seg][bT + qw + r4 + 8] = m1;
        g_ml[1][seg][bT + qw + r4 + 8] = l1;
    }
}

// ============================================================
// Combine: merge <=4 segments per row, normalize, write out.
// ============================================================
__global__ __launch_bounds__(256)
void comb_kernel(float* __restrict__ out)
{
    int gid = blockIdx.x * 256 + threadIdx.x;     // NROWS*32 threads
    int row = gid >> 5;
    int c4 = (gid & 31) * 4;
    int t = row & (T - 1);
    int qTile = t >> 7;
    int nseg = (2 * qTile + 2 + SEG - 1) / SEG;

    float m = -1e30f;
    #pragma unroll 4
    for (int s = 0; s < nseg; s++) m = fmaxf(m, g_ml[0][s][row]);
    float L = 0.f;
    float4 acc = make_float4(0.f, 0.f, 0.f, 0.f);
    #pragma unroll 4
    for (int s = 0; s < nseg; s++) {
        float w = exp2p(g_ml[0][s][row] - m);
        L += g_ml[1][s][row] * w;
        float4 o = *(float4*)&g_Op[s][(size_t)row * H + c4];
        acc.x += o.x * w; acc.y += o.y * w; acc.z += o.z * w; acc.w += o.w * w;
    }
    float inv = 1.0f / L;
    *(float4*)&out[(size_t)row * H + c4] =
        make_float4(acc.x * inv, acc.y * inv, acc.z * inv, acc.w * inv);
}

extern "C" void kernel_launch(void* const* d_in, const int* in_sizes, int n_in,
                              void* d_out, int out_size)
{
    const float* x  = (const float*)d_in[0];
    const float* Wq = (const float*)d_in[1];
    const float* Wk = (const float*)d_in[2];
    const float* Wv = (const float*)d_in[3];
    float* out = (float*)d_out;

    cudaFuncSetAttribute(mm_kernel, cudaFuncAttributeMaxDynamicSharedMemorySize, MM_SMEM);
    cudaFuncSetAttribute(attn_kernel, cudaFuncAttributeMaxDynamicSharedMemorySize, ATT_SMEM);

    split_x_kernel<<<NROWS * CDIM / 4 / 256, 256>>>(x);
    split_w_kernel<<<dim3(H * CDIM / 256, 3), 256>>>(Wq, Wk, Wv);
    mm_kernel<<<dim3(NROWS / 128, 3), 256, MM_SMEM>>>();
    attn_kernel<<<dim3(80, B), 256, ATT_SMEM>>>();
    comb_kernel<<<NROWS * 32 / 256, 256>>>(out);
}

// round 12
// speedup vs baseline: 3.8417x; 1.0607x over previous
#include <cuda_runtime.h>
#include <cuda_bf16.h>
#include <cstdint>
#include <math.h>

#define B 4
#define T 4096
#define CDIM 2048
#define H 128
#define NROWS (B*T)

// Scratch (device globals per harness rules)
__device__ __nv_bfloat16 g_xh[NROWS*CDIM];     // x hi split
__device__ __nv_bfloat16 g_xl[NROWS*CDIM];     // x lo split
__device__ __nv_bfloat16 g_Wh[3*H*CDIM];       // W packed [w][n][k] hi
__device__ __nv_bfloat16 g_Wl[3*H*CDIM];       // W packed [w][n][k] lo
__device__ __nv_bfloat16 g_Qh[NROWS*H];        // Q (scaled) hi  [row][d]
__device__ __nv_bfloat16 g_Ql[NROWS*H];
__device__ __nv_bfloat16 g_Kh[NROWS*H];        // K hi [row][d]
__device__ __nv_bfloat16 g_Kl[NROWS*H];
__device__ __nv_bfloat16 g_Vth[H*NROWS];       // V^T hi [d][row]
__device__ __nv_bfloat16 g_Vtl[H*NROWS];
// flash-decoding partials: up to 4 KV segments per q-tile
__device__ float g_Op[4][NROWS*H];
__device__ float g_ml[2][4][NROWS];

__device__ __forceinline__ uint32_t smem_u32(const void* p) {
    uint32_t a;
    asm("{ .reg .u64 t; cvta.to.shared.u64 t, %1; cvt.u32.u64 %0, t; }" : "=r"(a) : "l"(p));
    return a;
}

__device__ __forceinline__ void cp_async16(uint32_t dst, const void* src) {
    asm volatile("cp.async.cg.shared.global [%0], [%1], 16;" :: "r"(dst), "l"(src) : "memory");
}
#define CP_COMMIT() asm volatile("cp.async.commit_group;" ::: "memory")
#define CP_WAIT1()  asm volatile("cp.async.wait_group 1;" ::: "memory")
#define CP_WAIT0()  asm volatile("cp.async.wait_group 0;" ::: "memory")

__device__ __forceinline__ void ldsm4(uint32_t addr, uint32_t* r) {
    asm volatile("ldmatrix.sync.aligned.m8n8.x4.shared.b16 {%0,%1,%2,%3}, [%4];"
        : "=r"(r[0]), "=r"(r[1]), "=r"(r[2]), "=r"(r[3]) : "r"(addr));
}

__device__ __forceinline__ void mma16816(float* c, const uint32_t* a, uint32_t b0, uint32_t b1) {
    asm volatile("mma.sync.aligned.m16n8k16.row.col.f32.bf16.bf16.f32 "
        "{%0,%1,%2,%3}, {%4,%5,%6,%7}, {%8,%9}, {%0,%1,%2,%3};"
        : "+f"(c[0]), "+f"(c[1]), "+f"(c[2]), "+f"(c[3])
        : "r"(a[0]), "r"(a[1]), "r"(a[2]), "r"(a[3]), "r"(b0), "r"(b1));
}

// Scalar exp2 (combine kernel): Schraudolph round + deg-5 Taylor.
__device__ __forceinline__ float exp2p(float x) {
    x = fmaxf(x, -100.f);
    float t = x + 12582912.f;
    int k = __float_as_int(t) - 0x4B400000;
    float f = x - (t - 12582912.f);
    float r = 0.00133336f;
    r = fmaf(r, f, 0.00961813f);
    r = fmaf(r, f, 0.05550411f);
    r = fmaf(r, f, 0.24022651f);
    r = fmaf(r, f, 0.69314718f);
    r = fmaf(r, f, 1.0f);
    return __int_as_float(__float_as_int(r) + (k << 23));
}

// Packed 2-wide exp2 on the FMA pipe via f32x2.
// Scale: (bits(t)-0x4B400000)<<23 == bits(t)<<23 (mod 2^32; low 9 bits of the
// constant are zero). Fraction: MUST be computed as x - (t - C) — both steps
// Sterbenz-exact. ((x - t) + C rounds the fraction away at ULP=1 near 2^23:
// the R11 bug.)
__device__ __forceinline__ void exp2p2(float& a, float& b) {
    a = fmaxf(a, -100.f); b = fmaxf(b, -100.f);
    uint64_t x2, C, nC, n1, t2, s2, f2, r2, c;
    asm("mov.b64 %0, {%1,%2};" : "=l"(x2) : "f"(a), "f"(b));
    asm("mov.b64 %0, {%1,%1};" : "=l"(C)  : "f"(12582912.f));
    asm("mov.b64 %0, {%1,%1};" : "=l"(nC) : "f"(-12582912.f));
    asm("mov.b64 %0, {%1,%1};" : "=l"(n1) : "f"(-1.0f));
    asm("add.rn.f32x2 %0, %1, %2;" : "=l"(t2) : "l"(x2), "l"(C));
    float ta, tb;
    asm("mov.b64 {%0,%1}, %2;" : "=f"(ta), "=f"(tb) : "l"(t2));
    int ka = __float_as_int(ta) << 23;   // == k<<23 (mod 2^32)
    int kb = __float_as_int(tb) << 23;
    asm("add.rn.f32x2 %0, %1, %2;" : "=l"(s2) : "l"(t2), "l"(nC));            // round(x), exact
    asm("fma.rn.f32x2 %0, %1, %2, %3;" : "=l"(f2) : "l"(s2), "l"(n1), "l"(x2)); // x - round(x), exact
    asm("mov.b64 %0, {%1,%1};" : "=l"(r2) : "f"(0.00133336f));
    asm("mov.b64 %0, {%1,%1};" : "=l"(c) : "f"(0.00961813f));
    asm("fma.rn.f32x2 %0, %0, %1, %2;" : "+l"(r2) : "l"(f2), "l"(c));
    asm("mov.b64 %0, {%1,%1};" : "=l"(c) : "f"(0.05550411f));
    asm("fma.rn.f32x2 %0, %0, %1, %2;" : "+l"(r2) : "l"(f2), "l"(c));
    asm("mov.b64 %0, {%1,%1};" : "=l"(c) : "f"(0.24022651f));
    asm("fma.rn.f32x2 %0, %0, %1, %2;" : "+l"(r2) : "l"(f2), "l"(c));
    asm("mov.b64 %0, {%1,%1};" : "=l"(c) : "f"(0.69314718f));
    asm("fma.rn.f32x2 %0, %0, %1, %2;" : "+l"(r2) : "l"(f2), "l"(c));
    asm("mov.b64 %0, {%1,%1};" : "=l"(c) : "f"(1.0f));
    asm("fma.rn.f32x2 %0, %0, %1, %2;" : "+l"(r2) : "l"(f2), "l"(c));
    float ra, rb;
    asm("mov.b64 {%0,%1}, %2;" : "=f"(ra), "=f"(rb) : "l"(r2));
    a = __int_as_float(__float_as_int(ra) + ka);
    b = __int_as_float(__float_as_int(rb) + kb);
}

// pack two floats -> bf16x2 hi; residual bf16x2 lo. Uses packed fma for residual.
__device__ __forceinline__ uint32_t pack_hl(float a, float b, uint32_t& lo) {
    uint32_t h;
    asm("cvt.rn.bf16x2.f32 %0, %1, %2;" : "=r"(h) : "f"(b), "f"(a));  // {lo=a, hi=b}
    uint32_t abits = h << 16;
    uint32_t bbits = h & 0xFFFF0000u;
    uint64_t hv, ab, n1, d;
    asm("mov.b64 %0, {%1,%2};" : "=l"(hv) : "r"(abits), "r"(bbits));
    asm("mov.b64 %0, {%1,%2};" : "=l"(ab) : "f"(a), "f"(b));
    asm("mov.b64 %0, {%1,%1};" : "=l"(n1) : "f"(-1.0f));
    asm("fma.rn.f32x2 %0, %1, %2, %3;" : "=l"(d) : "l"(hv), "l"(n1), "l"(ab));
    float da, db;
    asm("mov.b64 {%0,%1}, %2;" : "=f"(da), "=f"(db) : "l"(d));
    asm("cvt.rn.bf16x2.f32 %0, %1, %2;" : "=r"(lo) : "f"(db), "f"(da));
    return h;
}

// ============================================================
// Split kernels: fp32 -> bf16 hi + lo
// ============================================================
__global__ __launch_bounds__(256) void split_x_kernel(const float* __restrict__ x)
{
    int i = blockIdx.x * 256 + threadIdx.x;
    float4 v = ((const float4*)x)[i];
    __nv_bfloat16 h0 = __float2bfloat16_rn(v.x);
    __nv_bfloat16 h1 = __float2bfloat16_rn(v.y);
    __nv_bfloat16 h2 = __float2bfloat16_rn(v.z);
    __nv_bfloat16 h3 = __float2bfloat16_rn(v.w);
    __nv_bfloat16 l0 = __float2bfloat16_rn(v.x - __bfloat162float(h0));
    __nv_bfloat16 l1 = __float2bfloat16_rn(v.y - __bfloat162float(h1));
    __nv_bfloat16 l2 = __float2bfloat16_rn(v.z - __bfloat162float(h2));
    __nv_bfloat16 l3 = __float2bfloat16_rn(v.w - __bfloat162float(h3));
    __nv_bfloat162* ph = (__nv_bfloat162*)g_xh;
    __nv_bfloat162* pl = (__nv_bfloat162*)g_xl;
    ph[2*i]   = __halves2bfloat162(h0, h1);
    ph[2*i+1] = __halves2bfloat162(h2, h3);
    pl[2*i]   = __halves2bfloat162(l0, l1);
    pl[2*i+1] = __halves2bfloat162(l2, l3);
}

__global__ __launch_bounds__(256) void split_w_kernel(const float* __restrict__ Wq,
                                                      const float* __restrict__ Wk,
                                                      const float* __restrict__ Wv)
{
    int w = blockIdx.y;
    const float* W = (w == 0) ? Wq : (w == 1) ? Wk : Wv;
    int idx = blockIdx.x * 256 + threadIdx.x;
    int n = idx >> 11;
    int k = idx & 2047;
    float v = W[(size_t)k * H + n];
    __nv_bfloat16 h = __float2bfloat16_rn(v);
    __nv_bfloat16 l = __float2bfloat16_rn(v - __bfloat162float(h));
    g_Wh[(size_t)w * H * CDIM + idx] = h;
    g_Wl[(size_t)w * H * CDIM + idx] = l;
}

// ============================================================
// HMMA projection GEMM. KC=64 (32 iters), ONE sync per iter, 3-stage cp.async.
// Row stride 144B (128B data + 16 pad): gcd(9,8)=1 -> ldmatrix conflict-free.
// ============================================================
#define KC 64
#define NITER (CDIM / KC)          // 32
#define RSB 144
#define MAT_B (128 * RSB)          // 18432
#define STAGE_B (4 * MAT_B)        // 73728
#define NSTAGE 3
#define MM_SMEM (NSTAGE * STAGE_B) // 221184

__global__ __launch_bounds__(256, 1)
void mm_kernel()
{
    extern __shared__ char dsm[];
    uint32_t sb = smem_u32(dsm);
    int tid = threadIdx.x;
    int lid = tid & 31, wid = tid >> 5;
    int wm = wid & 3, wn = wid >> 2;
    int mBase = blockIdx.x * 128;
    int wsel  = blockIdx.y;
    int nBase = wsel * 128;

    float acc[2][8][4];
    #pragma unroll
    for (int mt = 0; mt < 2; mt++)
        #pragma unroll
        for (int nt = 0; nt < 8; nt++)
            #pragma unroll
            for (int e = 0; e < 4; e++) acc[mt][nt][e] = 0.f;

    auto load_stage = [&](int stage, int k0) {
        uint32_t s = sb + stage * STAGE_B;
        #pragma unroll
        for (int t = 0; t < 4; t++) {
            int l2 = tid + t * 256;          // 0..1023
            int row = l2 >> 3, c8 = l2 & 7;  // 128 rows x 8 16B-chunks
            uint32_t d = s + row * RSB + c8 * 16;
            size_t goffA = (size_t)(mBase + row) * CDIM + k0 + c8 * 8;
            size_t goffB = (size_t)(nBase + row) * CDIM + k0 + c8 * 8;
            cp_async16(d + 0*MAT_B, g_xh + goffA);
            cp_async16(d + 1*MAT_B, g_xl + goffA);
            cp_async16(d + 2*MAT_B, g_Wh + goffB);
            cp_async16(d + 3*MAT_B, g_Wl + goffB);
        }
    };

    load_stage(0, 0);  CP_COMMIT();
    load_stage(1, KC); CP_COMMIT();

    int lrow = lid & 15, lkh = lid >> 4;

    for (int it = 0; it < NITER; it++) {
        CP_WAIT1();
        __syncthreads();                      // also orders stage reuse for next load
        if (it + 2 < NITER) load_stage((it + 2) % NSTAGE, (it + 2) * KC);
        CP_COMMIT();

        uint32_t s = sb + (it % NSTAGE) * STAGE_B;
        #pragma unroll
        for (int ks = 0; ks < 4; ks++) {
            uint32_t kOff = ks * 32 + lkh * 16;
            uint32_t a_hi[2][4], a_lo[2][4];
            #pragma unroll
            for (int mt = 0; mt < 2; mt++) {
                uint32_t ra = (wm * 32 + mt * 16 + lrow) * RSB + kOff;
                ldsm4(s + 0*MAT_B + ra, a_hi[mt]);
                ldsm4(s + 1*MAT_B + ra, a_lo[mt]);
            }
            uint32_t b_hi[4][4], b_lo[4][4];
            #pragma unroll
            for (int j = 0; j < 4; j++) {
                uint32_t rb = (wn * 64 + j * 16 + lrow) * RSB + kOff;
                ldsm4(s + 2*MAT_B + rb, b_hi[j]);
                ldsm4(s + 3*MAT_B + rb, b_lo[j]);
            }
            #pragma unroll
            for (int mt = 0; mt < 2; mt++)
                #pragma unroll
                for (int nt = 0; nt < 8; nt++) {
                    int j = nt >> 1, sel = nt & 1;
                    uint32_t bh0 = b_hi[j][sel], bh1 = b_hi[j][sel + 2];
                    uint32_t bl0 = b_lo[j][sel], bl1 = b_lo[j][sel + 2];
                    mma16816(acc[mt][nt], a_hi[mt], bh0, bh1);
                    mma16816(acc[mt][nt], a_hi[mt], bl0, bl1);
                    mma16816(acc[mt][nt], a_lo[mt], bh0, bh1);
                }
        }
        // no trailing sync: next iter's leading sync orders stage reuse
    }

    const float F = (wsel == 0) ? (powf(2048.0f, -0.05f) * 1.44269504089f) : 1.0f;
    #pragma unroll
    for (int mt = 0; mt < 2; mt++)
        #pragma unroll
        for (int nt = 0; nt < 8; nt++) {
            int row = mBase + wm * 32 + mt * 16 + (lid >> 2);
            int col = wn * 64 + nt * 8 + 2 * (lid & 3);
            float v0 = acc[mt][nt][0] * F, v1 = acc[mt][nt][1] * F;
            float v2 = acc[mt][nt][2] * F, v3 = acc[mt][nt][3] * F;
            if (wsel < 2) {
                __nv_bfloat16* oh = (wsel == 0) ? g_Qh : g_Kh;
                __nv_bfloat16* ol = (wsel == 0) ? g_Ql : g_Kl;
                uint32_t lo01, lo23;
                uint32_t hi01 = pack_hl(v0, v1, lo01);
                uint32_t hi23 = pack_hl(v2, v3, lo23);
                *(uint32_t*)&oh[(size_t)row * H + col]       = hi01;
                *(uint32_t*)&ol[(size_t)row * H + col]       = lo01;
                *(uint32_t*)&oh[(size_t)(row + 8) * H + col] = hi23;
                *(uint32_t*)&ol[(size_t)(row + 8) * H + col] = lo23;
            } else {
                __nv_bfloat16 h0 = __float2bfloat16_rn(v0);
                __nv_bfloat16 h1 = __float2bfloat16_rn(v1);
                __nv_bfloat16 h2 = __float2bfloat16_rn(v2);
                __nv_bfloat16 h3 = __float2bfloat16_rn(v3);
                g_Vth[(size_t)col       * NROWS + row]     = h0;
                g_Vth[(size_t)(col + 1) * NROWS + row]     = h1;
                g_Vth[(size_t)col       * NROWS + row + 8] = h2;
                g_Vth[(size_t)(col + 1) * NROWS + row + 8] = h3;
                g_Vtl[(size_t)col       * NROWS + row]     = __float2bfloat16_rn(v0 - __bfloat162float(h0));
                g_Vtl[(size_t)(col + 1) * NROWS + row]     = __float2bfloat16_rn(v1 - __bfloat162float(h1));
                g_Vtl[(size_t)col       * NROWS + row + 8] = __float2bfloat16_rn(v2 - __bfloat162float(h2));
                g_Vtl[(size_t)(col + 1) * NROWS + row + 8] = __float2bfloat16_rn(v3 - __bfloat162float(h3));
            }
        }
}

// ============================================================
// HMMA flash attention with KV-split (flash-decoding). Packed-FMA softmax.
// ============================================================
#define QROWB 272
#define AKROWB 272
#define AVROWB 144
#define AQ_OFF_H 0
#define AQ_OFF_L (128 * QROWB)
#define AQ_BYTES (2 * 128 * QROWB)
#define KH_OFF 0
#define KL_OFF (64 * AKROWB)
#define VTH_OFF (2 * 64 * AKROWB)
#define VTL_OFF (VTH_OFF + 128 * AVROWB)
#define ASTAGE_B (VTL_OFF + 128 * AVROWB)
#define ATT_SMEM (AQ_BYTES + 2 * ASTAGE_B)
#define SEG 16

__global__ __launch_bounds__(256, 1)
void attn_kernel()
{
    extern __shared__ char dsm[];
    uint32_t sb = smem_u32(dsm);
    int tid = threadIdx.x;
    int lid = tid & 31, wid = tid >> 5;
    int lrow = lid & 15, lkh = lid >> 4;
    int r4 = lid >> 2, c2 = 2 * (lid & 3);
    int b = blockIdx.y;

    int idx = blockIdx.x, qTile, seg;
    if (idx < 8)       { qTile = idx; seg = 0; }
    else if (idx < 24) { int r = idx - 8;  qTile = 8  + (r >> 1); seg = r & 1; }
    else if (idx < 48) { int r = idx - 24; qTile = 16 + r / 3;    seg = r % 3; }
    else               { int r = idx - 48; qTile = 24 + (r >> 2); seg = r & 3; }

    int qBase = qTile * 128;
    int bT = b * T;
    int cEnd0 = 2 * qTile + 2;
    int cBeg = seg * SEG;
    int cEnd = min(cBeg + SEG, cEnd0);
    int qw = qBase + wid * 16;

    #pragma unroll
    for (int t = 0; t < 8; t++) {
        int l2 = tid + t * 256;
        int row = l2 >> 4, c16 = l2 & 15;
        uint32_t d = sb + AQ_OFF_H + row * QROWB + c16 * 16;
        cp_async16(d, g_Qh + (size_t)(bT + qBase + row) * H + c16 * 8);
        cp_async16(d + AQ_OFF_L, g_Ql + (size_t)(bT + qBase + row) * H + c16 * 8);
    }

    auto load_kv = [&](int c) {
        uint32_t stg = sb + AQ_BYTES + (c & 1) * ASTAGE_B;
        int kvB = c * 64;
        #pragma unroll
        for (int t = 0; t < 4; t++) {
            int l2 = tid + t * 256;
            int row = l2 >> 4, c16 = l2 & 15;
            uint32_t d = stg + row * AKROWB + c16 * 16;
            cp_async16(d + KH_OFF, g_Kh + (size_t)(bT + kvB + row) * H + c16 * 8);
            cp_async16(d + KL_OFF, g_Kl + (size_t)(bT + kvB + row) * H + c16 * 8);
            int vrow = l2 >> 3, vc16 = l2 & 7;
            uint32_t dv = stg + vrow * AVROWB + vc16 * 16;
            cp_async16(dv + VTH_OFF, g_Vth + (size_t)vrow * NROWS + bT + kvB + vc16 * 8);
            cp_async16(dv + VTL_OFF, g_Vtl + (size_t)vrow * NROWS + bT + kvB + vc16 * 8);
        }
    };

    load_kv(cBeg);
    CP_COMMIT();

    float O[16][4];
    #pragma unroll
    for (int nt = 0; nt < 16; nt++)
        #pragma unroll
        for (int e = 0; e < 4; e++) O[nt][e] = 0.f;
    float m0 = -1e30f, m1 = -1e30f, l0 = 0.f, l1 = 0.f;

    for (int c = cBeg; c < cEnd; c++) {
        CP_WAIT0();
        __syncthreads();
        if (c + 1 < cEnd) load_kv(c + 1);
        CP_COMMIT();

        int kvBase = c * 64;
        if (kvBase <= qw + 15) {
            uint32_t stg = sb + AQ_BYTES + (c & 1) * ASTAGE_B;

            float sf[8][4];
            #pragma unroll
            for (int j = 0; j < 8; j++)
                #pragma unroll
                for (int e = 0; e < 4; e++) sf[j][e] = 0.f;

            uint32_t qa = sb + AQ_OFF_H + (wid * 16 + lrow) * QROWB + lkh * 16;
            #pragma unroll
            for (int k8 = 0; k8 < 8; k8++) {
                uint32_t ah[4], al[4];
                ldsm4(qa + k8 * 32, ah);
                ldsm4(qa + k8 * 32 + AQ_OFF_L, al);
                #pragma unroll
                for (int j4 = 0; j4 < 4; j4++) {
                    uint32_t ka = stg + (j4 * 16 + lrow) * AKROWB + k8 * 32 + lkh * 16;
                    uint32_t bh[4], bl[4];
                    ldsm4(ka + KH_OFF, bh);
                    ldsm4(ka + KL_OFF, bl);
                    #pragma unroll
                    for (int sel = 0; sel < 2; sel++) {
                        float* s8 = sf[j4 * 2 + sel];
                        mma16816(s8, ah, bh[sel], bh[sel + 2]);
                        mma16816(s8, ah, bl[sel], bl[sel + 2]);
                        mma16816(s8, al, bh[sel], bh[sel + 2]);
                    }
                }
            }

            if (kvBase + 63 > qw) {
                int q0 = qw + r4, q1 = q0 + 8;
                #pragma unroll
                for (int j = 0; j < 8; j++) {
                    int kvc = kvBase + j * 8 + c2;
                    if (kvc     > q0) sf[j][0] = -1e30f;
                    if (kvc + 1 > q0) sf[j][1] = -1e30f;
                    if (kvc     > q1) sf[j][2] = -1e30f;
                    if (kvc + 1 > q1) sf[j][3] = -1e30f;
                }
            }

            float mx0 = -1e30f, mx1 = -1e30f;
            #pragma unroll
            for (int j = 0; j < 8; j++) {
                mx0 = fmaxf(mx0, fmaxf(sf[j][0], sf[j][1]));
                mx1 = fmaxf(mx1, fmaxf(sf[j][2], sf[j][3]));
            }
            mx0 = fmaxf(mx0, __shfl_xor_sync(0xffffffffu, mx0, 1));
            mx0 = fmaxf(mx0, __shfl_xor_sync(0xffffffffu, mx0, 2));
            mx1 = fmaxf(mx1, __shfl_xor_sync(0xffffffffu, mx1, 1));
            mx1 = fmaxf(mx1, __shfl_xor_sync(0xffffffffu, mx1, 2));
            float mn0 = fmaxf(m0, mx0), mn1 = fmaxf(m1, mx1);
            float sc0 = m0 - mn0, sc1 = m1 - mn1;
            exp2p2(sc0, sc1);
            float sum0 = 0.f, sum1 = 0.f;
            #pragma unroll
            for (int j = 0; j < 8; j++) {
                sf[j][0] -= mn0; sf[j][1] -= mn0;
                sf[j][2] -= mn1; sf[j][3] -= mn1;
                exp2p2(sf[j][0], sf[j][1]);
                exp2p2(sf[j][2], sf[j][3]);
                sum0 += sf[j][0] + sf[j][1];
                sum1 += sf[j][2] + sf[j][3];
            }
            sum0 += __shfl_xor_sync(0xffffffffu, sum0, 1);
            sum0 += __shfl_xor_sync(0xffffffffu, sum0, 2);
            sum1 += __shfl_xor_sync(0xffffffffu, sum1, 1);
            sum1 += __shfl_xor_sync(0xffffffffu, sum1, 2);
            l0 = l0 * sc0 + sum0;
            l1 = l1 * sc1 + sum1;
            m0 = mn0; m1 = mn1;
            #pragma unroll
            for (int nt = 0; nt < 16; nt++) {
                O[nt][0] *= sc0; O[nt][1] *= sc0;
                O[nt][2] *= sc1; O[nt][3] *= sc1;
            }

            #pragma unroll
            for (int kk = 0; kk < 4; kk++) {
                uint32_t ph[4], pl[4];
                ph[0] = pack_hl(sf[2*kk][0],   sf[2*kk][1],   pl[0]);
                ph[1] = pack_hl(sf[2*kk][2],   sf[2*kk][3],   pl[1]);
                ph[2] = pack_hl(sf[2*kk+1][0], sf[2*kk+1][1], pl[2]);
                ph[3] = pack_hl(sf[2*kk+1][2], sf[2*kk+1][3], pl[3]);
                #pragma unroll
                for (int t = 0; t < 8; t++) {
                    uint32_t va = stg + (t * 16 + lrow) * AVROWB + kk * 32 + lkh * 16;
                    uint32_t vh[4], vl[4];
                    ldsm4(va + VTH_OFF, vh);
                    ldsm4(va + VTL_OFF, vl);
                    float* o0 = O[2*t];
                    float* o1 = O[2*t + 1];
                    mma16816(o0, ph, vh[0], vh[2]);
                    mma16816(o0, ph, vl[0], vl[2]);
                    mma16816(o0, pl, vh[0], vh[2]);
                    mma16816(o1, ph, vh[1], vh[3]);
                    mma16816(o1, ph, vl[1], vl[3]);
                    mma16816(o1, pl, vh[1], vh[3]);
                }
            }
        }
    }

    float* Op = g_Op[seg];
    size_t row0 = (size_t)(bT + qw + r4) * H;
    size_t row1 = (size_t)(bT + qw + r4 + 8) * H;
    #pragma unroll
    for (int nt = 0; nt < 16; nt++) {
        int col = nt * 8 + c2;
        *(float2*)&Op[row0 + col] = make_float2(O[nt][0], O[nt][1]);
        *(float2*)&Op[row1 + col] = make_float2(O[nt][2], O[nt][3]);
    }
    if ((lid & 3) == 0) {
        g_ml[0][seg][bT + qw + r4]     = m0;
        g_ml[1][seg][bT + qw + r4]     = l0;
        g_ml[0][seg][bT + qw + r4 + 8] = m1;
        g_ml[1][seg][bT + qw + r4 + 8] = l1;
    }
}

// ============================================================
// Combine: merge <=4 segments per row, normalize, write out.
// ============================================================
__global__ __launch_bounds__(256)
void comb_kernel(float* __restrict__ out)
{
    int gid = blockIdx.x * 256 + threadIdx.x;
    int row = gid >> 5;
    int c4 = (gid & 31) * 4;
    int t = row & (T - 1);
    int qTile = t >> 7;
    int nseg = (2 * qTile + 2 + SEG - 1) / SEG;

    float m = -1e30f;
    #pragma unroll 4
    for (int s = 0; s < nseg; s++) m = fmaxf(m, g_ml[0][s][row]);
    float L = 0.f;
    float4 acc = make_float4(0.f, 0.f, 0.f, 0.f);
    #pragma unroll 4
    for (int s = 0; s < nseg; s++) {
        float w = exp2p(g_ml[0][s][row] - m);
        L += g_ml[1][s][row] * w;
        float4 o = *(float4*)&g_Op[s][(size_t)row * H + c4];
        acc.x += o.x * w; acc.y += o.y * w; acc.z += o.z * w; acc.w += o.w * w;
    }
    float inv = 1.0f / L;
    *(float4*)&out[(size_t)row * H + c4] =
        make_float4(acc.x * inv, acc.y * inv, acc.z * inv, acc.w * inv);
}

extern "C" void kernel_launch(void* const* d_in, const int* in_sizes, int n_in,
                              void* d_out, int out_size)
{
    const float* x  = (const float*)d_in[0];
    const float* Wq = (const float*)d_in[1];
    const float* Wk = (const float*)d_in[2];
    const float* Wv = (const float*)d_in[3];
    float* out = (float*)d_out;

    cudaFuncSetAttribute(mm_kernel, cudaFuncAttributeMaxDynamicSharedMemorySize, MM_SMEM);
    cudaFuncSetAttribute(attn_kernel, cudaFuncAttributeMaxDynamicSharedMemorySize, ATT_SMEM);

    split_x_kernel<<<NROWS * CDIM / 4 / 256, 256>>>(x);
    split_w_kernel<<<dim3(H * CDIM / 256, 3), 256>>>(Wq, Wk, Wv);
    mm_kernel<<<dim3(NROWS / 128, 3), 256, MM_SMEM>>>();
    attn_kernel<<<dim3(80, B), 256, ATT_SMEM>>>();
    comb_kernel<<<NROWS * 32 / 256, 256>>>(out);
}

// round 13
// speedup vs baseline: 3.9448x; 1.0268x over previous
#include <cuda_runtime.h>
#include <cuda_bf16.h>
#include <cstdint>
#include <math.h>

#define B 4
#define T 4096
#define CDIM 2048
#define H 128
#define NROWS (B*T)

// Scratch (device globals per harness rules)
__device__ __nv_bfloat16 g_xh[NROWS*CDIM];     // x hi split
__device__ __nv_bfloat16 g_xl[NROWS*CDIM];     // x lo split
__device__ __nv_bfloat16 g_Wh[3*H*CDIM];       // W packed [w][n][k] hi
__device__ __nv_bfloat16 g_Wl[3*H*CDIM];       // W packed [w][n][k] lo
__device__ __nv_bfloat16 g_Qh[NROWS*H];        // Q (scaled) hi  [row][d]
__device__ __nv_bfloat16 g_Ql[NROWS*H];
__device__ __nv_bfloat16 g_Kh[NROWS*H];        // K hi [row][d]
__device__ __nv_bfloat16 g_Kl[NROWS*H];
__device__ __nv_bfloat16 g_Vth[H*NROWS];       // V^T hi [d][row]
__device__ __nv_bfloat16 g_Vtl[H*NROWS];
// flash-decoding partials: up to 4 KV segments per q-tile
__device__ float g_Op[4][NROWS*H];
__device__ float g_ml[2][4][NROWS];

__device__ __forceinline__ uint32_t smem_u32(const void* p) {
    uint32_t a;
    asm("{ .reg .u64 t; cvta.to.shared.u64 t, %1; cvt.u32.u64 %0, t; }" : "=r"(a) : "l"(p));
    return a;
}

__device__ __forceinline__ void cp_async16(uint32_t dst, const void* src) {
    asm volatile("cp.async.cg.shared.global [%0], [%1], 16;" :: "r"(dst), "l"(src) : "memory");
}
#define CP_COMMIT() asm volatile("cp.async.commit_group;" ::: "memory")
#define CP_WAIT1()  asm volatile("cp.async.wait_group 1;" ::: "memory")
#define CP_WAIT0()  asm volatile("cp.async.wait_group 0;" ::: "memory")

__device__ __forceinline__ void ldsm4(uint32_t addr, uint32_t* r) {
    asm volatile("ldmatrix.sync.aligned.m8n8.x4.shared.b16 {%0,%1,%2,%3}, [%4];"
        : "=r"(r[0]), "=r"(r[1]), "=r"(r[2]), "=r"(r[3]) : "r"(addr));
}

__device__ __forceinline__ void mma16816(float* c, const uint32_t* a, uint32_t b0, uint32_t b1) {
    asm volatile("mma.sync.aligned.m16n8k16.row.col.f32.bf16.bf16.f32 "
        "{%0,%1,%2,%3}, {%4,%5,%6,%7}, {%8,%9}, {%0,%1,%2,%3};"
        : "+f"(c[0]), "+f"(c[1]), "+f"(c[2]), "+f"(c[3])
        : "r"(a[0]), "r"(a[1]), "r"(a[2]), "r"(a[3]), "r"(b0), "r"(b1));
}

// Scalar exp2 (combine kernel): Schraudolph round + deg-5 Taylor.
__device__ __forceinline__ float exp2p(float x) {
    x = fmaxf(x, -100.f);
    float t = x + 12582912.f;
    int k = __float_as_int(t) - 0x4B400000;
    float f = x - (t - 12582912.f);
    float r = 0.00133336f;
    r = fmaf(r, f, 0.00961813f);
    r = fmaf(r, f, 0.05550411f);
    r = fmaf(r, f, 0.24022651f);
    r = fmaf(r, f, 0.69314718f);
    r = fmaf(r, f, 1.0f);
    return __int_as_float(__float_as_int(r) + (k << 23));
}

// Packed 2-wide exp2 on the FMA pipe via f32x2. Fraction via x - (t - C)
// (Sterbenz-exact both steps); scale via bits(t)<<23 (mod 2^32).
__device__ __forceinline__ void exp2p2(float& a, float& b) {
    a = fmaxf(a, -100.f); b = fmaxf(b, -100.f);
    uint64_t x2, C, nC, n1, t2, s2, f2, r2, c;
    asm("mov.b64 %0, {%1,%2};" : "=l"(x2) : "f"(a), "f"(b));
    asm("mov.b64 %0, {%1,%1};" : "=l"(C)  : "f"(12582912.f));
    asm("mov.b64 %0, {%1,%1};" : "=l"(nC) : "f"(-12582912.f));
    asm("mov.b64 %0, {%1,%1};" : "=l"(n1) : "f"(-1.0f));
    asm("add.rn.f32x2 %0, %1, %2;" : "=l"(t2) : "l"(x2), "l"(C));
    float ta, tb;
    asm("mov.b64 {%0,%1}, %2;" : "=f"(ta), "=f"(tb) : "l"(t2));
    int ka = __float_as_int(ta) << 23;
    int kb = __float_as_int(tb) << 23;
    asm("add.rn.f32x2 %0, %1, %2;" : "=l"(s2) : "l"(t2), "l"(nC));
    asm("fma.rn.f32x2 %0, %1, %2, %3;" : "=l"(f2) : "l"(s2), "l"(n1), "l"(x2));
    asm("mov.b64 %0, {%1,%1};" : "=l"(r2) : "f"(0.00133336f));
    asm("mov.b64 %0, {%1,%1};" : "=l"(c) : "f"(0.00961813f));
    asm("fma.rn.f32x2 %0, %0, %1, %2;" : "+l"(r2) : "l"(f2), "l"(c));
    asm("mov.b64 %0, {%1,%1};" : "=l"(c) : "f"(0.05550411f));
    asm("fma.rn.f32x2 %0, %0, %1, %2;" : "+l"(r2) : "l"(f2), "l"(c));
    asm("mov.b64 %0, {%1,%1};" : "=l"(c) : "f"(0.24022651f));
    asm("fma.rn.f32x2 %0, %0, %1, %2;" : "+l"(r2) : "l"(f2), "l"(c));
    asm("mov.b64 %0, {%1,%1};" : "=l"(c) : "f"(0.69314718f));
    asm("fma.rn.f32x2 %0, %0, %1, %2;" : "+l"(r2) : "l"(f2), "l"(c));
    asm("mov.b64 %0, {%1,%1};" : "=l"(c) : "f"(1.0f));
    asm("fma.rn.f32x2 %0, %0, %1, %2;" : "+l"(r2) : "l"(f2), "l"(c));
    float ra, rb;
    asm("mov.b64 {%0,%1}, %2;" : "=f"(ra), "=f"(rb) : "l"(r2));
    a = __int_as_float(__float_as_int(ra) + ka);
    b = __int_as_float(__float_as_int(rb) + kb);
}

// pack two floats -> bf16x2 hi; residual bf16x2 lo. Uses packed fma for residual.
__device__ __forceinline__ uint32_t pack_hl(float a, float b, uint32_t& lo) {
    uint32_t h;
    asm("cvt.rn.bf16x2.f32 %0, %1, %2;" : "=r"(h) : "f"(b), "f"(a));  // {lo=a, hi=b}
    uint32_t abits = h << 16;
    uint32_t bbits = h & 0xFFFF0000u;
    uint64_t hv, ab, n1, d;
    asm("mov.b64 %0, {%1,%2};" : "=l"(hv) : "r"(abits), "r"(bbits));
    asm("mov.b64 %0, {%1,%2};" : "=l"(ab) : "f"(a), "f"(b));
    asm("mov.b64 %0, {%1,%1};" : "=l"(n1) : "f"(-1.0f));
    asm("fma.rn.f32x2 %0, %1, %2, %3;" : "=l"(d) : "l"(hv), "l"(n1), "l"(ab));
    float da, db;
    asm("mov.b64 {%0,%1}, %2;" : "=f"(da), "=f"(db) : "l"(d));
    asm("cvt.rn.bf16x2.f32 %0, %1, %2;" : "=r"(lo) : "f"(db), "f"(da));
    return h;
}

// ============================================================
// Split kernels: fp32 -> bf16 hi + lo
// ============================================================
__global__ __launch_bounds__(256) void split_x_kernel(const float* __restrict__ x)
{
    int i = blockIdx.x * 256 + threadIdx.x;
    float4 v = ((const float4*)x)[i];
    __nv_bfloat16 h0 = __float2bfloat16_rn(v.x);
    __nv_bfloat16 h1 = __float2bfloat16_rn(v.y);
    __nv_bfloat16 h2 = __float2bfloat16_rn(v.z);
    __nv_bfloat16 h3 = __float2bfloat16_rn(v.w);
    __nv_bfloat16 l0 = __float2bfloat16_rn(v.x - __bfloat162float(h0));
    __nv_bfloat16 l1 = __float2bfloat16_rn(v.y - __bfloat162float(h1));
    __nv_bfloat16 l2 = __float2bfloat16_rn(v.z - __bfloat162float(h2));
    __nv_bfloat16 l3 = __float2bfloat16_rn(v.w - __bfloat162float(h3));
    __nv_bfloat162* ph = (__nv_bfloat162*)g_xh;
    __nv_bfloat162* pl = (__nv_bfloat162*)g_xl;
    ph[2*i]   = __halves2bfloat162(h0, h1);
    ph[2*i+1] = __halves2bfloat162(h2, h3);
    pl[2*i]   = __halves2bfloat162(l0, l1);
    pl[2*i+1] = __halves2bfloat162(l2, l3);
}

__global__ __launch_bounds__(256) void split_w_kernel(const float* __restrict__ Wq,
                                                      const float* __restrict__ Wk,
                                                      const float* __restrict__ Wv)
{
    int w = blockIdx.y;
    const float* W = (w == 0) ? Wq : (w == 1) ? Wk : Wv;
    int idx = blockIdx.x * 256 + threadIdx.x;
    int n = idx >> 11;
    int k = idx & 2047;
    float v = W[(size_t)k * H + n];
    __nv_bfloat16 h = __float2bfloat16_rn(v);
    __nv_bfloat16 l = __float2bfloat16_rn(v - __bfloat162float(h));
    g_Wh[(size_t)w * H * CDIM + idx] = h;
    g_Wl[(size_t)w * H * CDIM + idx] = l;
}

// ============================================================
// HMMA projection GEMM. 512 threads (16 warps, 4m x 4n, warp tile 32x32)
// -> 4 warps/SMSP for latency hiding. KC=64, one sync/iter, 3-stage cp.async.
// ============================================================
#define KC 64
#define NITER (CDIM / KC)          // 32
#define RSB 144
#define MAT_B (128 * RSB)          // 18432
#define STAGE_B (4 * MAT_B)        // 73728
#define NSTAGE 3
#define MM_SMEM (NSTAGE * STAGE_B) // 221184

__global__ __launch_bounds__(512, 1)
void mm_kernel()
{
    extern __shared__ char dsm[];
    uint32_t sb = smem_u32(dsm);
    int tid = threadIdx.x;
    int lid = tid & 31, wid = tid >> 5;
    int wm = wid & 3, wn = wid >> 2;         // 4m x 4n warp grid
    int mBase = blockIdx.x * 128;
    int wsel  = blockIdx.y;
    int nBase = wsel * 128;

    float acc[2][4][4];
    #pragma unroll
    for (int mt = 0; mt < 2; mt++)
        #pragma unroll
        for (int nt = 0; nt < 4; nt++)
            #pragma unroll
            for (int e = 0; e < 4; e++) acc[mt][nt][e] = 0.f;

    auto load_stage = [&](int stage, int k0) {
        uint32_t s = sb + stage * STAGE_B;
        #pragma unroll
        for (int t = 0; t < 2; t++) {
            int l2 = tid + t * 512;          // 0..1023
            int row = l2 >> 3, c8 = l2 & 7;  // 128 rows x 8 16B-chunks
            uint32_t d = s + row * RSB + c8 * 16;
            size_t goffA = (size_t)(mBase + row) * CDIM + k0 + c8 * 8;
            size_t goffB = (size_t)(nBase + row) * CDIM + k0 + c8 * 8;
            cp_async16(d + 0*MAT_B, g_xh + goffA);
            cp_async16(d + 1*MAT_B, g_xl + goffA);
            cp_async16(d + 2*MAT_B, g_Wh + goffB);
            cp_async16(d + 3*MAT_B, g_Wl + goffB);
        }
    };

    load_stage(0, 0);  CP_COMMIT();
    load_stage(1, KC); CP_COMMIT();

    int lrow = lid & 15, lkh = lid >> 4;

    for (int it = 0; it < NITER; it++) {
        CP_WAIT1();
        __syncthreads();                      // also orders stage reuse for next load
        if (it + 2 < NITER) load_stage((it + 2) % NSTAGE, (it + 2) * KC);
        CP_COMMIT();

        uint32_t s = sb + (it % NSTAGE) * STAGE_B;
        #pragma unroll
        for (int ks = 0; ks < 4; ks++) {
            uint32_t kOff = ks * 32 + lkh * 16;
            uint32_t a_hi[2][4], a_lo[2][4];
            #pragma unroll
            for (int mt = 0; mt < 2; mt++) {
                uint32_t ra = (wm * 32 + mt * 16 + lrow) * RSB + kOff;
                ldsm4(s + 0*MAT_B + ra, a_hi[mt]);
                ldsm4(s + 1*MAT_B + ra, a_lo[mt]);
            }
            uint32_t b_hi[2][4], b_lo[2][4];
            #pragma unroll
            for (int j = 0; j < 2; j++) {
                uint32_t rb = (wn * 32 + j * 16 + lrow) * RSB + kOff;
                ldsm4(s + 2*MAT_B + rb, b_hi[j]);
                ldsm4(s + 3*MAT_B + rb, b_lo[j]);
            }
            #pragma unroll
            for (int mt = 0; mt < 2; mt++)
                #pragma unroll
                for (int nt = 0; nt < 4; nt++) {
                    int j = nt >> 1, sel = nt & 1;
                    uint32_t bh0 = b_hi[j][sel], bh1 = b_hi[j][sel + 2];
                    uint32_t bl0 = b_lo[j][sel], bl1 = b_lo[j][sel + 2];
                    mma16816(acc[mt][nt], a_hi[mt], bh0, bh1);
                    mma16816(acc[mt][nt], a_hi[mt], bl0, bl1);
                    mma16816(acc[mt][nt], a_lo[mt], bh0, bh1);
                }
        }
        // no trailing sync: next iter's leading sync orders stage reuse
    }

    const float F = (wsel == 0) ? (powf(2048.0f, -0.05f) * 1.44269504089f) : 1.0f;
    #pragma unroll
    for (int mt = 0; mt < 2; mt++)
        #pragma unroll
        for (int nt = 0; nt < 4; nt++) {
            int row = mBase + wm * 32 + mt * 16 + (lid >> 2);
            int col = wn * 32 + nt * 8 + 2 * (lid & 3);
            float v0 = acc[mt][nt][0] * F, v1 = acc[mt][nt][1] * F;
            float v2 = acc[mt][nt][2] * F, v3 = acc[mt][nt][3] * F;
            if (wsel < 2) {
                __nv_bfloat16* oh = (wsel == 0) ? g_Qh : g_Kh;
                __nv_bfloat16* ol = (wsel == 0) ? g_Ql : g_Kl;
                uint32_t lo01, lo23;
                uint32_t hi01 = pack_hl(v0, v1, lo01);
                uint32_t hi23 = pack_hl(v2, v3, lo23);
                *(uint32_t*)&oh[(size_t)row * H + col]       = hi01;
                *(uint32_t*)&ol[(size_t)row * H + col]       = lo01;
                *(uint32_t*)&oh[(size_t)(row + 8) * H + col] = hi23;
                *(uint32_t*)&ol[(size_t)(row + 8) * H + col] = lo23;
            } else {
                __nv_bfloat16 h0 = __float2bfloat16_rn(v0);
                __nv_bfloat16 h1 = __float2bfloat16_rn(v1);
                __nv_bfloat16 h2 = __float2bfloat16_rn(v2);
                __nv_bfloat16 h3 = __float2bfloat16_rn(v3);
                g_Vth[(size_t)col       * NROWS + row]     = h0;
                g_Vth[(size_t)(col + 1) * NROWS + row]     = h1;
                g_Vth[(size_t)col       * NROWS + row + 8] = h2;
                g_Vth[(size_t)(col + 1) * NROWS + row + 8] = h3;
                g_Vtl[(size_t)col       * NROWS + row]     = __float2bfloat16_rn(v0 - __bfloat162float(h0));
                g_Vtl[(size_t)(col + 1) * NROWS + row]     = __float2bfloat16_rn(v1 - __bfloat162float(h1));
                g_Vtl[(size_t)col       * NROWS + row + 8] = __float2bfloat16_rn(v2 - __bfloat162float(h2));
                g_Vtl[(size_t)(col + 1) * NROWS + row + 8] = __float2bfloat16_rn(v3 - __bfloat162float(h3));
            }
        }
}

// ============================================================
// HMMA flash attention with KV-split (flash-decoding). Packed-FMA softmax.
// (unchanged from R12-passing version)
// ============================================================
#define QROWB 272
#define AKROWB 272
#define AVROWB 144
#define AQ_OFF_H 0
#define AQ_OFF_L (128 * QROWB)
#define AQ_BYTES (2 * 128 * QROWB)
#define KH_OFF 0
#define KL_OFF (64 * AKROWB)
#define VTH_OFF (2 * 64 * AKROWB)
#define VTL_OFF (VTH_OFF + 128 * AVROWB)
#define ASTAGE_B (VTL_OFF + 128 * AVROWB)
#define ATT_SMEM (AQ_BYTES + 2 * ASTAGE_B)
#define SEG 16

__global__ __launch_bounds__(256, 1)
void attn_kernel()
{
    extern __shared__ char dsm[];
    uint32_t sb = smem_u32(dsm);
    int tid = threadIdx.x;
    int lid = tid & 31, wid = tid >> 5;
    int lrow = lid & 15, lkh = lid >> 4;
    int r4 = lid >> 2, c2 = 2 * (lid & 3);
    int b = blockIdx.y;

    int idx = blockIdx.x, qTile, seg;
    if (idx < 8)       { qTile = idx; seg = 0; }
    else if (idx < 24) { int r = idx - 8;  qTile = 8  + (r >> 1); seg = r & 1; }
    else if (idx < 48) { int r = idx - 24; qTile = 16 + r / 3;    seg = r % 3; }
    else               { int r = idx - 48; qTile = 24 + (r >> 2); seg = r & 3; }

    int qBase = qTile * 128;
    int bT = b * T;
    int cEnd0 = 2 * qTile + 2;
    int cBeg = seg * SEG;
    int cEnd = min(cBeg + SEG, cEnd0);
    int qw = qBase + wid * 16;

    #pragma unroll
    for (int t = 0; t < 8; t++) {
        int l2 = tid + t * 256;
        int row = l2 >> 4, c16 = l2 & 15;
        uint32_t d = sb + AQ_OFF_H + row * QROWB + c16 * 16;
        cp_async16(d, g_Qh + (size_t)(bT + qBase + row) * H + c16 * 8);
        cp_async16(d + AQ_OFF_L, g_Ql + (size_t)(bT + qBase + row) * H + c16 * 8);
    }

    auto load_kv = [&](int c) {
        uint32_t stg = sb + AQ_BYTES + (c & 1) * ASTAGE_B;
        int kvB = c * 64;
        #pragma unroll
        for (int t = 0; t < 4; t++) {
            int l2 = tid + t * 256;
            int row = l2 >> 4, c16 = l2 & 15;
            uint32_t d = stg + row * AKROWB + c16 * 16;
            cp_async16(d + KH_OFF, g_Kh + (size_t)(bT + kvB + row) * H + c16 * 8);
            cp_async16(d + KL_OFF, g_Kl + (size_t)(bT + kvB + row) * H + c16 * 8);
            int vrow = l2 >> 3, vc16 = l2 & 7;
            uint32_t dv = stg + vrow * AVROWB + vc16 * 16;
            cp_async16(dv + VTH_OFF, g_Vth + (size_t)vrow * NROWS + bT + kvB + vc16 * 8);
            cp_async16(dv + VTL_OFF, g_Vtl + (size_t)vrow * NROWS + bT + kvB + vc16 * 8);
        }
    };

    load_kv(cBeg);
    CP_COMMIT();

    float O[16][4];
    #pragma unroll
    for (int nt = 0; nt < 16; nt++)
        #pragma unroll
        for (int e = 0; e < 4; e++) O[nt][e] = 0.f;
    float m0 = -1e30f, m1 = -1e30f, l0 = 0.f, l1 = 0.f;

    for (int c = cBeg; c < cEnd; c++) {
        CP_WAIT0();
        __syncthreads();
        if (c + 1 < cEnd) load_kv(c + 1);
        CP_COMMIT();

        int kvBase = c * 64;
        if (kvBase <= qw + 15) {
            uint32_t stg = sb + AQ_BYTES + (c & 1) * ASTAGE_B;

            float sf[8][4];
            #pragma unroll
            for (int j = 0; j < 8; j++)
                #pragma unroll
                for (int e = 0; e < 4; e++) sf[j][e] = 0.f;

            uint32_t qa = sb + AQ_OFF_H + (wid * 16 + lrow) * QROWB + lkh * 16;
            #pragma unroll
            for (int k8 = 0; k8 < 8; k8++) {
                uint32_t ah[4], al[4];
                ldsm4(qa + k8 * 32, ah);
                ldsm4(qa + k8 * 32 + AQ_OFF_L, al);
                #pragma unroll
                for (int j4 = 0; j4 < 4; j4++) {
                    uint32_t ka = stg + (j4 * 16 + lrow) * AKROWB + k8 * 32 + lkh * 16;
                    uint32_t bh[4], bl[4];
                    ldsm4(ka + KH_OFF, bh);
                    ldsm4(ka + KL_OFF, bl);
                    #pragma unroll
                    for (int sel = 0; sel < 2; sel++) {
                        float* s8 = sf[j4 * 2 + sel];
                        mma16816(s8, ah, bh[sel], bh[sel + 2]);
                        mma16816(s8, ah, bl[sel], bl[sel + 2]);
                        mma16816(s8, al, bh[sel], bh[sel + 2]);
                    }
                }
            }

            if (kvBase + 63 > qw) {
                int q0 = qw + r4, q1 = q0 + 8;
                #pragma unroll
                for (int j = 0; j < 8; j++) {
                    int kvc = kvBase + j * 8 + c2;
                    if (kvc     > q0) sf[j][0] = -1e30f;
                    if (kvc + 1 > q0) sf[j][1] = -1e30f;
                    if (kvc     > q1) sf[j][2] = -1e30f;
                    if (kvc + 1 > q1) sf[j][3] = -1e30f;
                }
            }

            float mx0 = -1e30f, mx1 = -1e30f;
            #pragma unroll
            for (int j = 0; j < 8; j++) {
                mx0 = fmaxf(mx0, fmaxf(sf[j][0], sf[j][1]));
                mx1 = fmaxf(mx1, fmaxf(sf[j][2], sf[j][3]));
            }
            mx0 = fmaxf(mx0, __shfl_xor_sync(0xffffffffu, mx0, 1));
            mx0 = fmaxf(mx0, __shfl_xor_sync(0xffffffffu, mx0, 2));
            mx1 = fmaxf(mx1, __shfl_xor_sync(0xffffffffu, mx1, 1));
            mx1 = fmaxf(mx1, __shfl_xor_sync(0xffffffffu, mx1, 2));
            float mn0 = fmaxf(m0, mx0), mn1 = fmaxf(m1, mx1);
            float sc0 = m0 - mn0, sc1 = m1 - mn1;
            exp2p2(sc0, sc1);
            float sum0 = 0.f, sum1 = 0.f;
            #pragma unroll
            for (int j = 0; j < 8; j++) {
                sf[j][0] -= mn0; sf[j][1] -= mn0;
                sf[j][2] -= mn1; sf[j][3] -= mn1;
                exp2p2(sf[j][0], sf[j][1]);
                exp2p2(sf[j][2], sf[j][3]);
                sum0 += sf[j][0] + sf[j][1];
                sum1 += sf[j][2] + sf[j][3];
            }
            sum0 += __shfl_xor_sync(0xffffffffu, sum0, 1);
            sum0 += __shfl_xor_sync(0xffffffffu, sum0, 2);
            sum1 += __shfl_xor_sync(0xffffffffu, sum1, 1);
            sum1 += __shfl_xor_sync(0xffffffffu, sum1, 2);
            l0 = l0 * sc0 + sum0;
            l1 = l1 * sc1 + sum1;
            m0 = mn0; m1 = mn1;
            #pragma unroll
            for (int nt = 0; nt < 16; nt++) {
                O[nt][0] *= sc0; O[nt][1] *= sc0;
                O[nt][2] *= sc1; O[nt][3] *= sc1;
            }

            #pragma unroll
            for (int kk = 0; kk < 4; kk++) {
                uint32_t ph[4], pl[4];
                ph[0] = pack_hl(sf[2*kk][0],   sf[2*kk][1],   pl[0]);
                ph[1] = pack_hl(sf[2*kk][2],   sf[2*kk][3],   pl[1]);
                ph[2] = pack_hl(sf[2*kk+1][0], sf[2*kk+1][1], pl[2]);
                ph[3] = pack_hl(sf[2*kk+1][2], sf[2*kk+1][3], pl[3]);
                #pragma unroll
                for (int t = 0; t < 8; t++) {
                    uint32_t va = stg + (t * 16 + lrow) * AVROWB + kk * 32 + lkh * 16;
                    uint32_t vh[4], vl[4];
                    ldsm4(va + VTH_OFF, vh);
                    ldsm4(va + VTL_OFF, vl);
                    float* o0 = O[2*t];
                    float* o1 = O[2*t + 1];
                    mma16816(o0, ph, vh[0], vh[2]);
                    mma16816(o0, ph, vl[0], vl[2]);
                    mma16816(o0, pl, vh[0], vh[2]);
                    mma16816(o1, ph, vh[1], vh[3]);
                    mma16816(o1, ph, vl[1], vl[3]);
                    mma16816(o1, pl, vh[1], vh[3]);
                }
            }
        }
    }

    float* Op = g_Op[seg];
    size_t row0 = (size_t)(bT + qw + r4) * H;
    size_t row1 = (size_t)(bT + qw + r4 + 8) * H;
    #pragma unroll
    for (int nt = 0; nt < 16; nt++) {
        int col = nt * 8 + c2;
        *(float2*)&Op[row0 + col] = make_float2(O[nt][0], O[nt][1]);
        *(float2*)&Op[row1 + col] = make_float2(O[nt][2], O[nt][3]);
    }
    if ((lid & 3) == 0) {
        g_ml[0][seg][bT + qw + r4]     = m0;
        g_ml[1][seg][bT + qw + r4]     = l0;
        g_ml[0][seg][bT + qw + r4 + 8] = m1;
        g_ml[1][seg][bT + qw + r4 + 8] = l1;
    }
}

// ============================================================
// Combine: merge <=4 segments per row, normalize, write out.
// ============================================================
__global__ __launch_bounds__(256)
void comb_kernel(float* __restrict__ out)
{
    int gid = blockIdx.x * 256 + threadIdx.x;
    int row = gid >> 5;
    int c4 = (gid & 31) * 4;
    int t = row & (T - 1);
    int qTile = t >> 7;
    int nseg = (2 * qTile + 2 + SEG - 1) / SEG;

    float m = -1e30f;
    #pragma unroll 4
    for (int s = 0; s < nseg; s++) m = fmaxf(m, g_ml[0][s][row]);
    float L = 0.f;
    float4 acc = make_float4(0.f, 0.f, 0.f, 0.f);
    #pragma unroll 4
    for (int s = 0; s < nseg; s++) {
        float w = exp2p(g_ml[0][s][row] - m);
        L += g_ml[1][s][row] * w;
        float4 o = *(float4*)&g_Op[s][(size_t)row * H + c4];
        acc.x += o.x * w; acc.y += o.y * w; acc.z += o.z * w; acc.w += o.w * w;
    }
    float inv = 1.0f / L;
    *(float4*)&out[(size_t)row * H + c4] =
        make_float4(acc.x * inv, acc.y * inv, acc.z * inv, acc.w * inv);
}

extern "C" void kernel_launch(void* const* d_in, const int* in_sizes, int n_in,
                              void* d_out, int out_size)
{
    const float* x  = (const float*)d_in[0];
    const float* Wq = (const float*)d_in[1];
    const float* Wk = (const float*)d_in[2];
    const float* Wv = (const float*)d_in[3];
    float* out = (float*)d_out;

    cudaFuncSetAttribute(mm_kernel, cudaFuncAttributeMaxDynamicSharedMemorySize, MM_SMEM);
    cudaFuncSetAttribute(attn_kernel, cudaFuncAttributeMaxDynamicSharedMemorySize, ATT_SMEM);

    split_x_kernel<<<NROWS * CDIM / 4 / 256, 256>>>(x);
    split_w_kernel<<<dim3(H * CDIM / 256, 3), 256>>>(Wq, Wk, Wv);
    mm_kernel<<<dim3(NROWS / 128, 3), 512, MM_SMEM>>>();
    attn_kernel<<<dim3(80, B), 256, ATT_SMEM>>>();
    comb_kernel<<<NROWS * 32 / 256, 256>>>(out);
}

// round 14
// speedup vs baseline: 4.4385x; 1.1251x over previous
#include <cuda_runtime.h>
#include <cuda_bf16.h>
#include <cuda_fp16.h>
#include <cstdint>
#include <math.h>

#define B 4
#define T 4096
#define CDIM 2048
#define H 128
#define NROWS (B*T)

// Scratch (device globals per harness rules)
__device__ __nv_bfloat16 g_xh[NROWS*CDIM];     // x hi split
__device__ __nv_bfloat16 g_xl[NROWS*CDIM];     // x lo split
__device__ __nv_bfloat16 g_Wh[3*H*CDIM];       // W packed [w][n][k] hi
__device__ __nv_bfloat16 g_Wl[3*H*CDIM];       // W packed [w][n][k] lo
__device__ __nv_bfloat16 g_Qh[NROWS*H];        // Q (scaled) hi  [row][d]
__device__ __nv_bfloat16 g_Ql[NROWS*H];
__device__ __nv_bfloat16 g_Kh[NROWS*H];        // K hi [row][d]
__device__ __nv_bfloat16 g_Kl[NROWS*H];
__device__ __half        g_Vt[H*NROWS];        // V^T fp16 [d][row]
// flash-decoding partials: up to 4 KV segments per q-tile
__device__ float g_Op[4][NROWS*H];
__device__ float g_ml[2][4][NROWS];

__device__ __forceinline__ uint32_t smem_u32(const void* p) {
    uint32_t a;
    asm("{ .reg .u64 t; cvta.to.shared.u64 t, %1; cvt.u32.u64 %0, t; }" : "=r"(a) : "l"(p));
    return a;
}

__device__ __forceinline__ void cp_async16(uint32_t dst, const void* src) {
    asm volatile("cp.async.cg.shared.global [%0], [%1], 16;" :: "r"(dst), "l"(src) : "memory");
}
#define CP_COMMIT() asm volatile("cp.async.commit_group;" ::: "memory")
#define CP_WAIT1()  asm volatile("cp.async.wait_group 1;" ::: "memory")
#define CP_WAIT0()  asm volatile("cp.async.wait_group 0;" ::: "memory")

__device__ __forceinline__ void ldsm4(uint32_t addr, uint32_t* r) {
    asm volatile("ldmatrix.sync.aligned.m8n8.x4.shared.b16 {%0,%1,%2,%3}, [%4];"
        : "=r"(r[0]), "=r"(r[1]), "=r"(r[2]), "=r"(r[3]) : "r"(addr));
}

__device__ __forceinline__ void mma16816(float* c, const uint32_t* a, uint32_t b0, uint32_t b1) {
    asm volatile("mma.sync.aligned.m16n8k16.row.col.f32.bf16.bf16.f32 "
        "{%0,%1,%2,%3}, {%4,%5,%6,%7}, {%8,%9}, {%0,%1,%2,%3};"
        : "+f"(c[0]), "+f"(c[1]), "+f"(c[2]), "+f"(c[3])
        : "r"(a[0]), "r"(a[1]), "r"(a[2]), "r"(a[3]), "r"(b0), "r"(b1));
}

__device__ __forceinline__ void mma16816h(float* c, const uint32_t* a, uint32_t b0, uint32_t b1) {
    asm volatile("mma.sync.aligned.m16n8k16.row.col.f32.f16.f16.f32 "
        "{%0,%1,%2,%3}, {%4,%5,%6,%7}, {%8,%9}, {%0,%1,%2,%3};"
        : "+f"(c[0]), "+f"(c[1]), "+f"(c[2]), "+f"(c[3])
        : "r"(a[0]), "r"(a[1]), "r"(a[2]), "r"(a[3]), "r"(b0), "r"(b1));
}

// Scalar exp2 (combine kernel): Schraudolph round + deg-5 Taylor.
__device__ __forceinline__ float exp2p(float x) {
    x = fmaxf(x, -100.f);
    float t = x + 12582912.f;
    int k = __float_as_int(t) - 0x4B400000;
    float f = x - (t - 12582912.f);
    float r = 0.00133336f;
    r = fmaf(r, f, 0.00961813f);
    r = fmaf(r, f, 0.05550411f);
    r = fmaf(r, f, 0.24022651f);
    r = fmaf(r, f, 0.69314718f);
    r = fmaf(r, f, 1.0f);
    return __int_as_float(__float_as_int(r) + (k << 23));
}

// Packed 2-wide exp2 on the FMA pipe via f32x2. Fraction via x - (t - C)
// (Sterbenz-exact both steps); scale via bits(t)<<23 (mod 2^32).
__device__ __forceinline__ void exp2p2(float& a, float& b) {
    a = fmaxf(a, -100.f); b = fmaxf(b, -100.f);
    uint64_t x2, C, nC, n1, t2, s2, f2, r2, c;
    asm("mov.b64 %0, {%1,%2};" : "=l"(x2) : "f"(a), "f"(b));
    asm("mov.b64 %0, {%1,%1};" : "=l"(C)  : "f"(12582912.f));
    asm("mov.b64 %0, {%1,%1};" : "=l"(nC) : "f"(-12582912.f));
    asm("mov.b64 %0, {%1,%1};" : "=l"(n1) : "f"(-1.0f));
    asm("add.rn.f32x2 %0, %1, %2;" : "=l"(t2) : "l"(x2), "l"(C));
    float ta, tb;
    asm("mov.b64 {%0,%1}, %2;" : "=f"(ta), "=f"(tb) : "l"(t2));
    int ka = __float_as_int(ta) << 23;
    int kb = __float_as_int(tb) << 23;
    asm("add.rn.f32x2 %0, %1, %2;" : "=l"(s2) : "l"(t2), "l"(nC));
    asm("fma.rn.f32x2 %0, %1, %2, %3;" : "=l"(f2) : "l"(s2), "l"(n1), "l"(x2));
    asm("mov.b64 %0, {%1,%1};" : "=l"(r2) : "f"(0.00133336f));
    asm("mov.b64 %0, {%1,%1};" : "=l"(c) : "f"(0.00961813f));
    asm("fma.rn.f32x2 %0, %0, %1, %2;" : "+l"(r2) : "l"(f2), "l"(c));
    asm("mov.b64 %0, {%1,%1};" : "=l"(c) : "f"(0.05550411f));
    asm("fma.rn.f32x2 %0, %0, %1, %2;" : "+l"(r2) : "l"(f2), "l"(c));
    asm("mov.b64 %0, {%1,%1};" : "=l"(c) : "f"(0.24022651f));
    asm("fma.rn.f32x2 %0, %0, %1, %2;" : "+l"(r2) : "l"(f2), "l"(c));
    asm("mov.b64 %0, {%1,%1};" : "=l"(c) : "f"(0.69314718f));
    asm("fma.rn.f32x2 %0, %0, %1, %2;" : "+l"(r2) : "l"(f2), "l"(c));
    asm("mov.b64 %0, {%1,%1};" : "=l"(c) : "f"(1.0f));
    asm("fma.rn.f32x2 %0, %0, %1, %2;" : "+l"(r2) : "l"(f2), "l"(c));
    float ra, rb;
    asm("mov.b64 {%0,%1}, %2;" : "=f"(ra), "=f"(rb) : "l"(r2));
    a = __int_as_float(__float_as_int(ra) + ka);
    b = __int_as_float(__float_as_int(rb) + kb);
}

// pack two floats -> bf16x2 hi; residual bf16x2 lo. Uses packed fma for residual.
__device__ __forceinline__ uint32_t pack_hl(float a, float b, uint32_t& lo) {
    uint32_t h;
    asm("cvt.rn.bf16x2.f32 %0, %1, %2;" : "=r"(h) : "f"(b), "f"(a));  // {lo=a, hi=b}
    uint32_t abits = h << 16;
    uint32_t bbits = h & 0xFFFF0000u;
    uint64_t hv, ab, n1, d;
    asm("mov.b64 %0, {%1,%2};" : "=l"(hv) : "r"(abits), "r"(bbits));
    asm("mov.b64 %0, {%1,%2};" : "=l"(ab) : "f"(a), "f"(b));
    asm("mov.b64 %0, {%1,%1};" : "=l"(n1) : "f"(-1.0f));
    asm("fma.rn.f32x2 %0, %1, %2, %3;" : "=l"(d) : "l"(hv), "l"(n1), "l"(ab));
    float da, db;
    asm("mov.b64 {%0,%1}, %2;" : "=f"(da), "=f"(db) : "l"(d));
    asm("cvt.rn.bf16x2.f32 %0, %1, %2;" : "=r"(lo) : "f"(db), "f"(da));
    return h;
}

// ============================================================
// Split kernels: fp32 -> bf16 hi + lo
// ============================================================
__global__ __launch_bounds__(256) void split_x_kernel(const float* __restrict__ x)
{
    int i = blockIdx.x * 256 + threadIdx.x;
    float4 v = ((const float4*)x)[i];
    __nv_bfloat16 h0 = __float2bfloat16_rn(v.x);
    __nv_bfloat16 h1 = __float2bfloat16_rn(v.y);
    __nv_bfloat16 h2 = __float2bfloat16_rn(v.z);
    __nv_bfloat16 h3 = __float2bfloat16_rn(v.w);
    __nv_bfloat16 l0 = __float2bfloat16_rn(v.x - __bfloat162float(h0));
    __nv_bfloat16 l1 = __float2bfloat16_rn(v.y - __bfloat162float(h1));
    __nv_bfloat16 l2 = __float2bfloat16_rn(v.z - __bfloat162float(h2));
    __nv_bfloat16 l3 = __float2bfloat16_rn(v.w - __bfloat162float(h3));
    __nv_bfloat162* ph = (__nv_bfloat162*)g_xh;
    __nv_bfloat162* pl = (__nv_bfloat162*)g_xl;
    ph[2*i]   = __halves2bfloat162(h0, h1);
    ph[2*i+1] = __halves2bfloat162(h2, h3);
    pl[2*i]   = __halves2bfloat162(l0, l1);
    pl[2*i+1] = __halves2bfloat162(l2, l3);
}

__global__ __launch_bounds__(256) void split_w_kernel(const float* __restrict__ Wq,
                                                      const float* __restrict__ Wk,
                                                      const float* __restrict__ Wv)
{
    int w = blockIdx.y;
    const float* W = (w == 0) ? Wq : (w == 1) ? Wk : Wv;
    int idx = blockIdx.x * 256 + threadIdx.x;
    int n = idx >> 11;
    int k = idx & 2047;
    float v = W[(size_t)k * H + n];
    __nv_bfloat16 h = __float2bfloat16_rn(v);
    __nv_bfloat16 l = __float2bfloat16_rn(v - __bfloat162float(h));
    g_Wh[(size_t)w * H * CDIM + idx] = h;
    g_Wl[(size_t)w * H * CDIM + idx] = l;
}

// ============================================================
// HMMA projection GEMM. 512 threads (16 warps, 4m x 4n, warp tile 32x32).
// KC=64, one sync/iter, 3-stage cp.async. V epilogue -> single fp16 V^T.
// ============================================================
#define KC 64
#define NITER (CDIM / KC)          // 32
#define RSB 144
#define MAT_B (128 * RSB)          // 18432
#define STAGE_B (4 * MAT_B)        // 73728
#define NSTAGE 3
#define MM_SMEM (NSTAGE * STAGE_B) // 221184

__global__ __launch_bounds__(512, 1)
void mm_kernel()
{
    extern __shared__ char dsm[];
    uint32_t sb = smem_u32(dsm);
    int tid = threadIdx.x;
    int lid = tid & 31, wid = tid >> 5;
    int wm = wid & 3, wn = wid >> 2;         // 4m x 4n warp grid
    int mBase = blockIdx.x * 128;
    int wsel  = blockIdx.y;
    int nBase = wsel * 128;

    float acc[2][4][4];
    #pragma unroll
    for (int mt = 0; mt < 2; mt++)
        #pragma unroll
        for (int nt = 0; nt < 4; nt++)
            #pragma unroll
            for (int e = 0; e < 4; e++) acc[mt][nt][e] = 0.f;

    auto load_stage = [&](int stage, int k0) {
        uint32_t s = sb + stage * STAGE_B;
        #pragma unroll
        for (int t = 0; t < 2; t++) {
            int l2 = tid + t * 512;
            int row = l2 >> 3, c8 = l2 & 7;
            uint32_t d = s + row * RSB + c8 * 16;
            size_t goffA = (size_t)(mBase + row) * CDIM + k0 + c8 * 8;
            size_t goffB = (size_t)(nBase + row) * CDIM + k0 + c8 * 8;
            cp_async16(d + 0*MAT_B, g_xh + goffA);
            cp_async16(d + 1*MAT_B, g_xl + goffA);
            cp_async16(d + 2*MAT_B, g_Wh + goffB);
            cp_async16(d + 3*MAT_B, g_Wl + goffB);
        }
    };

    load_stage(0, 0);  CP_COMMIT();
    load_stage(1, KC); CP_COMMIT();

    int lrow = lid & 15, lkh = lid >> 4;

    for (int it = 0; it < NITER; it++) {
        CP_WAIT1();
        __syncthreads();
        if (it + 2 < NITER) load_stage((it + 2) % NSTAGE, (it + 2) * KC);
        CP_COMMIT();

        uint32_t s = sb + (it % NSTAGE) * STAGE_B;
        #pragma unroll
        for (int ks = 0; ks < 4; ks++) {
            uint32_t kOff = ks * 32 + lkh * 16;
            uint32_t a_hi[2][4], a_lo[2][4];
            #pragma unroll
            for (int mt = 0; mt < 2; mt++) {
                uint32_t ra = (wm * 32 + mt * 16 + lrow) * RSB + kOff;
                ldsm4(s + 0*MAT_B + ra, a_hi[mt]);
                ldsm4(s + 1*MAT_B + ra, a_lo[mt]);
            }
            uint32_t b_hi[2][4], b_lo[2][4];
            #pragma unroll
            for (int j = 0; j < 2; j++) {
                uint32_t rb = (wn * 32 + j * 16 + lrow) * RSB + kOff;
                ldsm4(s + 2*MAT_B + rb, b_hi[j]);
                ldsm4(s + 3*MAT_B + rb, b_lo[j]);
            }
            #pragma unroll
            for (int mt = 0; mt < 2; mt++)
                #pragma unroll
                for (int nt = 0; nt < 4; nt++) {
                    int j = nt >> 1, sel = nt & 1;
                    uint32_t bh0 = b_hi[j][sel], bh1 = b_hi[j][sel + 2];
                    uint32_t bl0 = b_lo[j][sel], bl1 = b_lo[j][sel + 2];
                    mma16816(acc[mt][nt], a_hi[mt], bh0, bh1);
                    mma16816(acc[mt][nt], a_hi[mt], bl0, bl1);
                    mma16816(acc[mt][nt], a_lo[mt], bh0, bh1);
                }
        }
    }

    const float F = (wsel == 0) ? (powf(2048.0f, -0.05f) * 1.44269504089f) : 1.0f;
    #pragma unroll
    for (int mt = 0; mt < 2; mt++)
        #pragma unroll
        for (int nt = 0; nt < 4; nt++) {
            int row = mBase + wm * 32 + mt * 16 + (lid >> 2);
            int col = wn * 32 + nt * 8 + 2 * (lid & 3);
            float v0 = acc[mt][nt][0] * F, v1 = acc[mt][nt][1] * F;
            float v2 = acc[mt][nt][2] * F, v3 = acc[mt][nt][3] * F;
            if (wsel < 2) {
                __nv_bfloat16* oh = (wsel == 0) ? g_Qh : g_Kh;
                __nv_bfloat16* ol = (wsel == 0) ? g_Ql : g_Kl;
                uint32_t lo01, lo23;
                uint32_t hi01 = pack_hl(v0, v1, lo01);
                uint32_t hi23 = pack_hl(v2, v3, lo23);
                *(uint32_t*)&oh[(size_t)row * H + col]       = hi01;
                *(uint32_t*)&ol[(size_t)row * H + col]       = lo01;
                *(uint32_t*)&oh[(size_t)(row + 8) * H + col] = hi23;
                *(uint32_t*)&ol[(size_t)(row + 8) * H + col] = lo23;
            } else {
                // V transposed, single fp16
                g_Vt[(size_t)col       * NROWS + row]     = __float2half_rn(v0);
                g_Vt[(size_t)(col + 1) * NROWS + row]     = __float2half_rn(v1);
                g_Vt[(size_t)col       * NROWS + row + 8] = __float2half_rn(v2);
                g_Vt[(size_t)(col + 1) * NROWS + row + 8] = __float2half_rn(v3);
            }
        }
}

// ============================================================
// HMMA flash attention with KV-split. S: 3-term bf16. PV: single fp16 MMA.
// ============================================================
#define QROWB 272
#define AKROWB 272
#define AVROWB 144
#define AQ_OFF_H 0
#define AQ_OFF_L (128 * QROWB)
#define AQ_BYTES (2 * 128 * QROWB)
#define KH_OFF 0
#define KL_OFF (64 * AKROWB)
#define VTH_OFF (2 * 64 * AKROWB)
#define ASTAGE_B (VTH_OFF + 128 * AVROWB)   // 53248
#define ATT_SMEM (AQ_BYTES + 2 * ASTAGE_B)  // 176128
#define SEG 16

__global__ __launch_bounds__(256, 1)
void attn_kernel()
{
    extern __shared__ char dsm[];
    uint32_t sb = smem_u32(dsm);
    int tid = threadIdx.x;
    int lid = tid & 31, wid = tid >> 5;
    int lrow = lid & 15, lkh = lid >> 4;
    int r4 = lid >> 2, c2 = 2 * (lid & 3);
    int b = blockIdx.y;

    int idx = blockIdx.x, qTile, seg;
    if (idx < 8)       { qTile = idx; seg = 0; }
    else if (idx < 24) { int r = idx - 8;  qTile = 8  + (r >> 1); seg = r & 1; }
    else if (idx < 48) { int r = idx - 24; qTile = 16 + r / 3;    seg = r % 3; }
    else               { int r = idx - 48; qTile = 24 + (r >> 2); seg = r & 3; }

    int qBase = qTile * 128;
    int bT = b * T;
    int cEnd0 = 2 * qTile + 2;
    int cBeg = seg * SEG;
    int cEnd = min(cBeg + SEG, cEnd0);
    int qw = qBase + wid * 16;

    #pragma unroll
    for (int t = 0; t < 8; t++) {
        int l2 = tid + t * 256;
        int row = l2 >> 4, c16 = l2 & 15;
        uint32_t d = sb + AQ_OFF_H + row * QROWB + c16 * 16;
        cp_async16(d, g_Qh + (size_t)(bT + qBase + row) * H + c16 * 8);
        cp_async16(d + AQ_OFF_L, g_Ql + (size_t)(bT + qBase + row) * H + c16 * 8);
    }

    auto load_kv = [&](int c) {
        uint32_t stg = sb + AQ_BYTES + (c & 1) * ASTAGE_B;
        int kvB = c * 64;
        #pragma unroll
        for (int t = 0; t < 4; t++) {
            int l2 = tid + t * 256;
            int row = l2 >> 4, c16 = l2 & 15;
            uint32_t d = stg + row * AKROWB + c16 * 16;
            cp_async16(d + KH_OFF, g_Kh + (size_t)(bT + kvB + row) * H + c16 * 8);
            cp_async16(d + KL_OFF, g_Kl + (size_t)(bT + kvB + row) * H + c16 * 8);
            int vrow = l2 >> 3, vc16 = l2 & 7;
            uint32_t dv = stg + vrow * AVROWB + vc16 * 16;
            cp_async16(dv + VTH_OFF, g_Vt + (size_t)vrow * NROWS + bT + kvB + vc16 * 8);
        }
    };

    load_kv(cBeg);
    CP_COMMIT();

    float O[16][4];
    #pragma unroll
    for (int nt = 0; nt < 16; nt++)
        #pragma unroll
        for (int e = 0; e < 4; e++) O[nt][e] = 0.f;
    float m0 = -1e30f, m1 = -1e30f, l0 = 0.f, l1 = 0.f;

    for (int c = cBeg; c < cEnd; c++) {
        CP_WAIT0();
        __syncthreads();
        if (c + 1 < cEnd) load_kv(c + 1);
        CP_COMMIT();

        int kvBase = c * 64;
        if (kvBase <= qw + 15) {
            uint32_t stg = sb + AQ_BYTES + (c & 1) * ASTAGE_B;

            float sf[8][4];
            #pragma unroll
            for (int j = 0; j < 8; j++)
                #pragma unroll
                for (int e = 0; e < 4; e++) sf[j][e] = 0.f;

            uint32_t qa = sb + AQ_OFF_H + (wid * 16 + lrow) * QROWB + lkh * 16;
            #pragma unroll
            for (int k8 = 0; k8 < 8; k8++) {
                uint32_t ah[4], al[4];
                ldsm4(qa + k8 * 32, ah);
                ldsm4(qa + k8 * 32 + AQ_OFF_L, al);
                #pragma unroll
                for (int j4 = 0; j4 < 4; j4++) {
                    uint32_t ka = stg + (j4 * 16 + lrow) * AKROWB + k8 * 32 + lkh * 16;
                    uint32_t bh[4], bl[4];
                    ldsm4(ka + KH_OFF, bh);
                    ldsm4(ka + KL_OFF, bl);
                    #pragma unroll
                    for (int sel = 0; sel < 2; sel++) {
                        float* s8 = sf[j4 * 2 + sel];
                        mma16816(s8, ah, bh[sel], bh[sel + 2]);
                        mma16816(s8, ah, bl[sel], bl[sel + 2]);
                        mma16816(s8, al, bh[sel], bh[sel + 2]);
                    }
                }
            }

            if (kvBase + 63 > qw) {
                int q0 = qw + r4, q1 = q0 + 8;
                #pragma unroll
                for (int j = 0; j < 8; j++) {
                    int kvc = kvBase + j * 8 + c2;
                    if (kvc     > q0) sf[j][0] = -1e30f;
                    if (kvc + 1 > q0) sf[j][1] = -1e30f;
                    if (kvc     > q1) sf[j][2] = -1e30f;
                    if (kvc + 1 > q1) sf[j][3] = -1e30f;
                }
            }

            float mx0 = -1e30f, mx1 = -1e30f;
            #pragma unroll
            for (int j = 0; j < 8; j++) {
                mx0 = fmaxf(mx0, fmaxf(sf[j][0], sf[j][1]));
                mx1 = fmaxf(mx1, fmaxf(sf[j][2], sf[j][3]));
            }
            mx0 = fmaxf(mx0, __shfl_xor_sync(0xffffffffu, mx0, 1));
            mx0 = fmaxf(mx0, __shfl_xor_sync(0xffffffffu, mx0, 2));
            mx1 = fmaxf(mx1, __shfl_xor_sync(0xffffffffu, mx1, 1));
            mx1 = fmaxf(mx1, __shfl_xor_sync(0xffffffffu, mx1, 2));
            float mn0 = fmaxf(m0, mx0), mn1 = fmaxf(m1, mx1);
            float sc0 = m0 - mn0, sc1 = m1 - mn1;
            exp2p2(sc0, sc1);
            float sum0 = 0.f, sum1 = 0.f;
            #pragma unroll
            for (int j = 0; j < 8; j++) {
                sf[j][0] -= mn0; sf[j][1] -= mn0;
                sf[j][2] -= mn1; sf[j][3] -= mn1;
                exp2p2(sf[j][0], sf[j][1]);
                exp2p2(sf[j][2], sf[j][3]);
                sum0 += sf[j][0] + sf[j][1];
                sum1 += sf[j][2] + sf[j][3];
            }
            sum0 += __shfl_xor_sync(0xffffffffu, sum0, 1);
            sum0 += __shfl_xor_sync(0xffffffffu, sum0, 2);
            sum1 += __shfl_xor_sync(0xffffffffu, sum1, 1);
            sum1 += __shfl_xor_sync(0xffffffffu, sum1, 2);
            l0 = l0 * sc0 + sum0;
            l1 = l1 * sc1 + sum1;
            m0 = mn0; m1 = mn1;
            #pragma unroll
            for (int nt = 0; nt < 16; nt++) {
                O[nt][0] *= sc0; O[nt][1] *= sc0;
                O[nt][2] *= sc1; O[nt][3] *= sc1;
            }

            // ---- O += P V : single fp16 MMA per tile ----
            #pragma unroll
            for (int kk = 0; kk < 4; kk++) {
                uint32_t ph[4];
                asm("cvt.rn.f16x2.f32 %0, %1, %2;" : "=r"(ph[0]) : "f"(sf[2*kk][1]),   "f"(sf[2*kk][0]));
                asm("cvt.rn.f16x2.f32 %0, %1, %2;" : "=r"(ph[1]) : "f"(sf[2*kk][3]),   "f"(sf[2*kk][2]));
                asm("cvt.rn.f16x2.f32 %0, %1, %2;" : "=r"(ph[2]) : "f"(sf[2*kk+1][1]), "f"(sf[2*kk+1][0]));
                asm("cvt.rn.f16x2.f32 %0, %1, %2;" : "=r"(ph[3]) : "f"(sf[2*kk+1][3]), "f"(sf[2*kk+1][2]));
                #pragma unroll
                for (int t = 0; t < 8; t++) {
                    uint32_t va = stg + (t * 16 + lrow) * AVROWB + kk * 32 + lkh * 16;
                    uint32_t vh[4];
                    ldsm4(va + VTH_OFF, vh);
                    mma16816h(O[2*t],     ph, vh[0], vh[2]);
                    mma16816h(O[2*t + 1], ph, vh[1], vh[3]);
                }
            }
        }
    }

    float* Op = g_Op[seg];
    size_t row0 = (size_t)(bT + qw + r4) * H;
    size_t row1 = (size_t)(bT + qw + r4 + 8) * H;
    #pragma unroll
    for (int nt = 0; nt < 16; nt++) {
        int col = nt * 8 + c2;
        *(float2*)&Op[row0 + col] = make_float2(O[nt][0], O[nt][1]);
        *(float2*)&Op[row1 + col] = make_float2(O[nt][2], O[nt][3]);
    }
    if ((lid & 3) == 0) {
        g_ml[0][seg][bT + qw + r4]     = m0;
        g_ml[1][seg][bT + qw + r4]     = l0;
        g_ml[0][seg][bT + qw + r4 + 8] = m1;
        g_ml[1][seg][bT + qw + r4 + 8] = l1;
    }
}

// ============================================================
// Combine: merge <=4 segments per row, normalize, write out.
// ============================================================
__global__ __launch_bounds__(256)
void comb_kernel(float* __restrict__ out)
{
    int gid = blockIdx.x * 256 + threadIdx.x;
    int row = gid >> 5;
    int c4 = (gid & 31) * 4;
    int t = row & (T - 1);
    int qTile = t >> 7;
    int nseg = (2 * qTile + 2 + SEG - 1) / SEG;

    float m = -1e30f;
    #pragma unroll 4
    for (int s = 0; s < nseg; s++) m = fmaxf(m, g_ml[0][s][row]);
    float L = 0.f;
    float4 acc = make_float4(0.f, 0.f, 0.f, 0.f);
    #pragma unroll 4
    for (int s = 0; s < nseg; s++) {
        float w = exp2p(g_ml[0][s][row] - m);
        L += g_ml[1][s][row] * w;
        float4 o = *(float4*)&g_Op[s][(size_t)row * H + c4];
        acc.x += o.x * w; acc.y += o.y * w; acc.z += o.z * w; acc.w += o.w * w;
    }
    float inv = 1.0f / L;
    *(float4*)&out[(size_t)row * H + c4] =
        make_float4(acc.x * inv, acc.y * inv, acc.z * inv, acc.w * inv);
}

extern "C" void kernel_launch(void* const* d_in, const int* in_sizes, int n_in,
                              void* d_out, int out_size)
{
    const float* x  = (const float*)d_in[0];
    const float* Wq = (const float*)d_in[1];
    const float* Wk = (const float*)d_in[2];
    const float* Wv = (const float*)d_in[3];
    float* out = (float*)d_out;

    cudaFuncSetAttribute(mm_kernel, cudaFuncAttributeMaxDynamicSharedMemorySize, MM_SMEM);
    cudaFuncSetAttribute(attn_kernel, cudaFuncAttributeMaxDynamicSharedMemorySize, ATT_SMEM);

    split_x_kernel<<<NROWS * CDIM / 4 / 256, 256>>>(x);
    split_w_kernel<<<dim3(H * CDIM / 256, 3), 256>>>(Wq, Wk, Wv);
    mm_kernel<<<dim3(NROWS / 128, 3), 512, MM_SMEM>>>();
    attn_kernel<<<dim3(80, B), 256, ATT_SMEM>>>();
    comb_kernel<<<NROWS * 32 / 256, 256>>>(out);
}